// round 14
// baseline (speedup 1.0000x reference)
#include <cuda_runtime.h>
#include <cuda_fp16.h>
#include <cstdint>
#include <math.h>

#define Bx 4
#define Sx 1024
#define Hx 1024
#define NHx 16
#define HDx 64
#define BR_HEADS 4
#define BR_HD 256
static const float CAUSAL_W = 0.7f;
static const float META_W  = 0.15f;

#define MB (Bx * Sx)   // 4096 rows

// ---------------------------------------------------------------------------
// Device scratch (fp16 hi/lo splits)
// ---------------------------------------------------------------------------
__device__ __half g_xs_hi[MB * Hx];
__device__ __half g_wqkvT_hi[3 * Hx * Hx], g_wqkvT_lo[3 * Hx * Hx];   // [WqT;WkT;WvT]
__device__ __half g_caWinT_hi[3 * Hx * Hx], g_caWinT_lo[3 * Hx * Hx];
__device__ __half g_caWoutT_hi[Hx * Hx],    g_caWoutT_lo[Hx * Hx];
__device__ __half g_mcWinT_hi[3 * Hx * Hx], g_mcWinT_lo[3 * Hx * Hx];
__device__ __half g_mcWoutT_hi[Hx * Hx],    g_mcWoutT_lo[Hx * Hx];
__device__ __half g_woT_hi[Hx * Hx], g_woT_lo[Hx * Hx];
__device__ float  g_bqkv[3 * Hx];

__device__ __half g_qk_hi[MB * 2 * Hx], g_qk_lo[MB * 2 * Hx];   // [m][q(1024) k(1024)]
__device__ __half g_vT_hi[MB * Hx], g_vT_lo[MB * Hx];           // [b][d][s]
__device__ __half g_qkv_hi[MB * 3 * Hx], g_qkv_lo[MB * 3 * Hx];

__device__ float g_ctx [MB * Hx];
__device__ float g_ctxb[MB * Hx];
__device__ __half g_ctx2_hi[MB * Hx];
__device__ __half g_ctxb_hi[MB * Hx];
__device__ __half g_ctxm_hi[MB * Hx];
__device__ float g_mod[MB * NHx];

// ---------------------------------------------------------------------------
// PTX helpers
// ---------------------------------------------------------------------------
__device__ __forceinline__ uint32_t smem_u32(const void* p) {
    uint32_t a;
    asm("{ .reg .u64 t; cvta.to.shared.u64 t, %1; cvt.u32.u64 %0, t; }" : "=r"(a) : "l"(p));
    return a;
}
#define SWZ128(o) ((o) ^ (((o) >> 3) & 0x70))

__device__ __forceinline__ void cp16(uint32_t s, const void* g) {
    asm volatile("cp.async.cg.shared.global [%0], [%1], 16;"
                 :: "r"(s), "l"(__cvta_generic_to_global(g)) : "memory");
}
#define CP_COMMIT() asm volatile("cp.async.commit_group;" ::: "memory")
template<int N> __device__ __forceinline__ void cp_wait() {
    asm volatile("cp.async.wait_group %0;" :: "n"(N) : "memory");
}
__device__ __forceinline__ void ldmx4(uint32_t* r, uint32_t a) {
    asm volatile("ldmatrix.sync.aligned.m8n8.x4.shared.b16 {%0,%1,%2,%3}, [%4];"
        : "=r"(r[0]), "=r"(r[1]), "=r"(r[2]), "=r"(r[3]) : "r"(a));
}
__device__ __forceinline__ void ldmx4t(uint32_t* r, uint32_t a) {
    asm volatile("ldmatrix.sync.aligned.m8n8.x4.trans.shared.b16 {%0,%1,%2,%3}, [%4];"
        : "=r"(r[0]), "=r"(r[1]), "=r"(r[2]), "=r"(r[3]) : "r"(a));
}
__device__ __forceinline__ void mma_f32(float* c, const uint32_t* a, const uint32_t* b) {
    asm volatile(
        "mma.sync.aligned.m16n8k16.row.col.f32.f16.f16.f32 "
        "{%0,%1,%2,%3}, {%4,%5,%6,%7}, {%8,%9}, {%0,%1,%2,%3};"
        : "+f"(c[0]), "+f"(c[1]), "+f"(c[2]), "+f"(c[3])
        : "r"(a[0]), "r"(a[1]), "r"(a[2]), "r"(a[3]), "r"(b[0]), "r"(b[1]));
}
__device__ __forceinline__ uint32_t pack_h2(float x, float y) {
    uint32_t r;
    asm("cvt.rn.f16x2.f32 %0, %1, %2;" : "=r"(r) : "f"(y), "f"(x));
    return r;
}

// ---------------------------------------------------------------------------
// 2-term fp16 GEMM: C = alpha*(Ah @ (Bh+Bl)^T + bias) + beta*blend.
// BM=128 x BN=128, BK=64, 8 warps (2m x 4n), warp tile 64x32.
// 2-stage cp.async, stage = A 16K | B_hi 16K | B_lo 16K = 48K -> 2 CTAs/SM.
// Smem intensity ~12 units/byte (was 8 at BN=64).
// ---------------------------------------------------------------------------
__global__ void __launch_bounds__(256, 2) gemm128(
    const __half* __restrict__ Ah, int lda, long sA1, long sA2,
    const __half* __restrict__ Bh, const __half* __restrict__ Bl,
    int ldb, long sB1, long sB2,
    float* Cf, __half* Chi, __half* Clo,
    int ldc, long sC1, long sC2,
    __half* Thi, __half* Tlo, int tn0, int tn1, long TB,
    int K, int Z2,
    const float* __restrict__ bias, float alpha,
    const float* __restrict__ blend, int ldbl, float beta)
{
    constexpr int BSTG = 49152;
    extern __shared__ char dsm[];
    uint32_t sb = smem_u32(dsm);

    const int z = blockIdx.z, z1 = z / Z2, z2 = z % Z2;
    {
        Ah += z1 * sA1 + z2 * sA2;
        long bo = z1 * sB1 + z2 * sB2;
        Bh += bo; Bl += bo;
        long co = z1 * sC1 + z2 * sC2;
        if (Cf)  Cf  += co;
        if (Chi) Chi += co;
        if (Clo) Clo += co;
    }

    const int tid = threadIdx.x, lane = tid & 31, wid = tid >> 5;
    const int wm = wid >> 2, wn = wid & 3;           // 2m x 4n warp grid
    const int m0 = blockIdx.y * 128, n0 = blockIdx.x * 128;

    float acc[4][4][4];                              // mt x nt x frag (64 regs)
#pragma unroll
    for (int a = 0; a < 4; a++)
#pragma unroll
        for (int b = 0; b < 4; b++)
#pragma unroll
            for (int cc = 0; cc < 4; cc++) acc[a][b][cc] = 0.f;

    const int nk = K >> 6;

    auto fill = [&](int st, int c) {
        const int k0 = c << 6;
        const uint32_t base = sb + st * BSTG;
        for (int i = tid; i < 1024; i += 256) {       // A: 128 rows x 8 groups
            int row = i >> 3, gb = (i & 7) * 16;
            uint32_t sw = SWZ128(row * 128 + gb);
            cp16(base + sw, Ah + (long)(m0 + row) * lda + k0 + (gb >> 1));
        }
        for (int i = tid; i < 1024; i += 256) {       // B: 128 rows x 8 groups, hi+lo
            int row = i >> 3, gb = (i & 7) * 16;
            uint32_t sw = SWZ128(row * 128 + gb);
            long go = (long)(n0 + row) * ldb + k0 + (gb >> 1);
            cp16(base + 16384 + sw, Bh + go);
            cp16(base + 32768 + sw, Bl + go);
        }
    };

    const int rA = (lane & 7) + ((lane >> 3) & 1) * 8;
    const int cA = ((lane >> 4) & 1) * 16;
    const int rB = (lane & 7) + ((lane >> 4) & 1) * 8;
    const int cB = ((lane >> 3) & 1) * 16;

    fill(0, 0); CP_COMMIT();
    for (int c = 0; c < nk; c++) {
        if (c + 1 < nk) { fill((c + 1) & 1, c + 1); CP_COMMIT(); cp_wait<1>(); }
        else cp_wait<0>();
        __syncthreads();
        const uint32_t base = sb + (c & 1) * BSTG;
#pragma unroll
        for (int ks = 0; ks < 4; ks++) {
            uint32_t bh[4][2], bl[4][2];
#pragma unroll
            for (int n2 = 0; n2 < 2; n2++) {
                uint32_t r[4];
                uint32_t bd = base + 16384 + SWZ128((wn * 32 + n2 * 16 + rB) * 128 + ks * 32 + cB);
                ldmx4(r, bd);
                bh[2*n2][0] = r[0]; bh[2*n2][1] = r[1];
                bh[2*n2+1][0] = r[2]; bh[2*n2+1][1] = r[3];
                ldmx4(r, bd + 16384);
                bl[2*n2][0] = r[0]; bl[2*n2][1] = r[1];
                bl[2*n2+1][0] = r[2]; bl[2*n2+1][1] = r[3];
            }
            uint32_t ah[4][4];
#pragma unroll
            for (int mt = 0; mt < 4; mt++) {
                uint32_t ad = base + SWZ128((wm * 64 + mt * 16 + rA) * 128 + ks * 32 + cA);
                ldmx4(ah[mt], ad);
            }
#pragma unroll
            for (int mt = 0; mt < 4; mt++)
#pragma unroll
                for (int nt = 0; nt < 4; nt++)
                    mma_f32(acc[mt][nt], ah[mt], bh[nt]);
#pragma unroll
            for (int mt = 0; mt < 4; mt++)
#pragma unroll
                for (int nt = 0; nt < 4; nt++)
                    mma_f32(acc[mt][nt], ah[mt], bl[nt]);
        }
        __syncthreads();
    }

    const int gid = lane >> 2, tig = lane & 3;
    auto store2 = [&](int m, int n, float v0, float v1) {
        if (bias) { v0 += bias[n]; v1 += bias[n + 1]; }
        v0 *= alpha; v1 *= alpha;
        if (blend) {
            const float* bp = blend + (long)m * ldbl + n;
            v0 += beta * bp[0]; v1 += beta * bp[1];
        }
        if (Cf) *(float2*)(Cf + (long)m * ldc + n) = make_float2(v0, v1);
        if (Chi && (!Thi || n < tn0)) {
            __half h0 = __float2half(v0), h1 = __float2half(v1);
            long o = (long)m * ldc + n;
            *(__half2*)(Chi + o) = __halves2half2(h0, h1);
            if (Clo)
                *(__half2*)(Clo + o) = __halves2half2(
                    __float2half(v0 - __half2float(h0)), __float2half(v1 - __half2float(h1)));
        }
        if (Thi && n >= tn0 && n < tn1) {
            __half h0 = __float2half(v0), h1 = __float2half(v1);
            long o = (long)(m >> 10) * TB + (long)(n - tn0) * 1024 + (m & 1023);
            Thi[o] = h0;        Tlo[o] = __float2half(v0 - __half2float(h0));
            Thi[o + 1024] = h1; Tlo[o + 1024] = __float2half(v1 - __half2float(h1));
        }
    };
#pragma unroll
    for (int mt = 0; mt < 4; mt++)
#pragma unroll
        for (int nt = 0; nt < 4; nt++) {
            int m = m0 + wm * 64 + mt * 16 + gid;
            int n = n0 + wn * 32 + nt * 8 + tig * 2;
            store2(m,     n, acc[mt][nt][0], acc[mt][nt][1]);
            store2(m + 8, n, acc[mt][nt][2], acc[mt][nt][3]);
        }
}

// ---------------------------------------------------------------------------
// Flash attention, main branch (HD=64, mod-gated, 2-term).  (as R13)
// ---------------------------------------------------------------------------
__global__ void __launch_bounds__(256) flash_main(
    const __half* __restrict__ qk_hi, const __half* __restrict__ qk_lo,
    const __half* __restrict__ vth_g, const __half* __restrict__ vtl_g,
    const float* __restrict__ mod, float* __restrict__ ctx)
{
    constexpr int OFF_KV = 16384, KVST = 32768;
    extern __shared__ char dsm[];
    uint32_t sb = smem_u32(dsm);

    const int z = blockIdx.y, b = z >> 4, h = z & 15;
    const int m0 = blockIdx.x * 128;
    const int tid = threadIdx.x, lane = tid & 31, wid = tid >> 5;
    const int gid = lane >> 2, tig = lane & 3;
    const long SHl = (long)Sx * Hx;

    const int rA = (lane & 7) + ((lane >> 3) & 1) * 8;
    const int cA = ((lane >> 4) & 1) * 16;
    const int rB = (lane & 7) + ((lane >> 4) & 1) * 8;
    const int cB = ((lane >> 3) & 1) * 16;

    for (int i = tid; i < 1024; i += 256) {
        int row = i >> 3, ch = i & 7;
        uint32_t sw = SWZ128(row * 128 + ch * 16);
        long go = (long)(b * Sx + m0 + row) * 2048 + h * 64 + ch * 8;
        cp16(sb + sw, qk_hi + go);
    }
    auto fillKV = [&](int st, int t) {
        const int kb = t * 64;
        const uint32_t base = sb + OFF_KV + st * KVST;
        for (int i = tid; i < 512; i += 256) {
            int row = i >> 3, ch = i & 7;
            uint32_t sw = SWZ128(row * 128 + ch * 16);
            long gk = (long)(b * Sx + kb + row) * 2048 + 1024 + h * 64 + ch * 8;
            long gv = (long)b * SHl + (long)(h * 64 + row) * Sx + kb + ch * 8;
            cp16(base + sw,          qk_hi + gk);
            cp16(base + 8192 + sw,   qk_lo + gk);
            cp16(base + 16384 + sw,  vth_g + gv);
            cp16(base + 24576 + sw,  vtl_g + gv);
        }
    };
    fillKV(0, 0);
    CP_COMMIT();

    const int r0 = m0 + wid * 16 + gid;
    const float msc0 = 0.125f * mod[(long)(b * Sx + r0) * NHx + h];
    const float msc1 = 0.125f * mod[(long)(b * Sx + r0 + 8) * NHx + h];

    uint32_t qh[4][4];
    float o[8][4];
#pragma unroll
    for (int nt = 0; nt < 8; nt++)
#pragma unroll
        for (int c = 0; c < 4; c++) o[nt][c] = 0.f;
    float m0_ = -1e30f, m1_ = -1e30f, l0_ = 0.f, l1_ = 0.f;

    const int NTILE = Sx / 64;
    for (int t = 0; t < NTILE; t++) {
        if (t + 1 < NTILE) { fillKV((t + 1) & 1, t + 1); CP_COMMIT(); cp_wait<1>(); }
        else cp_wait<0>();
        __syncthreads();
        const uint32_t base = sb + OFF_KV + (t & 1) * KVST;

        if (t == 0) {
#pragma unroll
            for (int ks = 0; ks < 4; ks++) {
                uint32_t ad = sb + SWZ128((wid * 16 + rA) * 128 + ks * 32 + cA);
                ldmx4(qh[ks], ad);
            }
        }

        float s[8][4];
#pragma unroll
        for (int nt = 0; nt < 8; nt++)
#pragma unroll
            for (int c = 0; c < 4; c++) s[nt][c] = 0.f;
#pragma unroll
        for (int ks = 0; ks < 4; ks++) {
            uint32_t bh[8][2], bl[8][2];
#pragma unroll
            for (int n2 = 0; n2 < 4; n2++) {
                uint32_t r[4];
                uint32_t bd = base + SWZ128((n2 * 16 + rB) * 128 + ks * 32 + cB);
                ldmx4(r, bd);
                bh[2*n2][0] = r[0]; bh[2*n2][1] = r[1];
                bh[2*n2+1][0] = r[2]; bh[2*n2+1][1] = r[3];
                ldmx4(r, bd + 8192);
                bl[2*n2][0] = r[0]; bl[2*n2][1] = r[1];
                bl[2*n2+1][0] = r[2]; bl[2*n2+1][1] = r[3];
            }
#pragma unroll
            for (int nt = 0; nt < 8; nt++) mma_f32(s[nt], qh[ks], bh[nt]);
#pragma unroll
            for (int nt = 0; nt < 8; nt++) mma_f32(s[nt], qh[ks], bl[nt]);
        }

        float mx0 = -1e30f, mx1 = -1e30f;
#pragma unroll
        for (int nt = 0; nt < 8; nt++) {
            s[nt][0] *= msc0; s[nt][1] *= msc0;
            s[nt][2] *= msc1; s[nt][3] *= msc1;
            mx0 = fmaxf(mx0, fmaxf(s[nt][0], s[nt][1]));
            mx1 = fmaxf(mx1, fmaxf(s[nt][2], s[nt][3]));
        }
        mx0 = fmaxf(mx0, __shfl_xor_sync(0xffffffffu, mx0, 1));
        mx0 = fmaxf(mx0, __shfl_xor_sync(0xffffffffu, mx0, 2));
        mx1 = fmaxf(mx1, __shfl_xor_sync(0xffffffffu, mx1, 1));
        mx1 = fmaxf(mx1, __shfl_xor_sync(0xffffffffu, mx1, 2));
        float mn0 = fmaxf(m0_, mx0), mn1 = fmaxf(m1_, mx1);
        float cr0 = __expf(m0_ - mn0), cr1 = __expf(m1_ - mn1);
        m0_ = mn0; m1_ = mn1;
        float sum0 = 0.f, sum1 = 0.f;
#pragma unroll
        for (int nt = 0; nt < 8; nt++) {
            s[nt][0] = __expf(s[nt][0] - mn0); sum0 += s[nt][0];
            s[nt][1] = __expf(s[nt][1] - mn0); sum0 += s[nt][1];
            s[nt][2] = __expf(s[nt][2] - mn1); sum1 += s[nt][2];
            s[nt][3] = __expf(s[nt][3] - mn1); sum1 += s[nt][3];
        }
        sum0 += __shfl_xor_sync(0xffffffffu, sum0, 1);
        sum0 += __shfl_xor_sync(0xffffffffu, sum0, 2);
        sum1 += __shfl_xor_sync(0xffffffffu, sum1, 1);
        sum1 += __shfl_xor_sync(0xffffffffu, sum1, 2);
        l0_ = l0_ * cr0 + sum0;
        l1_ = l1_ * cr1 + sum1;
#pragma unroll
        for (int nt = 0; nt < 8; nt++) {
            o[nt][0] *= cr0; o[nt][1] *= cr0;
            o[nt][2] *= cr1; o[nt][3] *= cr1;
        }

#pragma unroll
        for (int j = 0; j < 4; j++) {
            uint32_t pah[4];
            pah[0] = pack_h2(s[2*j][0],   s[2*j][1]);
            pah[1] = pack_h2(s[2*j][2],   s[2*j][3]);
            pah[2] = pack_h2(s[2*j+1][0], s[2*j+1][1]);
            pah[3] = pack_h2(s[2*j+1][2], s[2*j+1][3]);
            uint32_t vh[8][2], vl[8][2];
#pragma unroll
            for (int n2 = 0; n2 < 4; n2++) {
                uint32_t r[4];
                uint32_t bd = base + 16384 + SWZ128((n2 * 16 + rB) * 128 + j * 32 + cB);
                ldmx4(r, bd);
                vh[2*n2][0] = r[0]; vh[2*n2][1] = r[1];
                vh[2*n2+1][0] = r[2]; vh[2*n2+1][1] = r[3];
                ldmx4(r, bd + 8192);
                vl[2*n2][0] = r[0]; vl[2*n2][1] = r[1];
                vl[2*n2+1][0] = r[2]; vl[2*n2+1][1] = r[3];
            }
#pragma unroll
            for (int nt = 0; nt < 8; nt++) mma_f32(o[nt], pah, vh[nt]);
#pragma unroll
            for (int nt = 0; nt < 8; nt++) mma_f32(o[nt], pah, vl[nt]);
        }
        __syncthreads();
    }

    float inv0 = 1.f / l0_, inv1 = 1.f / l1_;
    const long row0 = (long)(b * Sx + r0) * Hx + h * 64;
    const long row1 = (long)(b * Sx + r0 + 8) * Hx + h * 64;
#pragma unroll
    for (int nt = 0; nt < 8; nt++) {
        int d = nt * 8 + tig * 2;
        *(float2*)(ctx + row0 + d) = make_float2(o[nt][0] * inv0, o[nt][1] * inv0);
        *(float2*)(ctx + row1 + d) = make_float2(o[nt][2] * inv1, o[nt][3] * inv1);
    }
}

// ---------------------------------------------------------------------------
// Flash attention, branch (HD=256, 4 heads, scale 1/16).  2-term,
// double-buffered KV.  (as R13)
// ---------------------------------------------------------------------------
__global__ void __launch_bounds__(128, 2) flash_branch(
    const __half* __restrict__ qkv_hi, const __half* __restrict__ qkv_lo,
    __half* __restrict__ chi)
{
    constexpr int OFF_KV = 32768, KVST = 32768;
    extern __shared__ char dsm[];
    uint32_t sb = smem_u32(dsm);

    const int b = blockIdx.y >> 2, h = blockIdx.y & 3;
    const int m0 = blockIdx.x * 64;
    const int tid = threadIdx.x, lane = tid & 31, wid = tid >> 5;
    const int gid = lane >> 2, tig = lane & 3;

    const int rA = (lane & 7) + ((lane >> 3) & 1) * 8;
    const int cA = ((lane >> 4) & 1) * 16;
    const int rB = (lane & 7) + ((lane >> 4) & 1) * 8;
    const int cB = ((lane >> 3) & 1) * 16;
    const int rV = lane & 15, cV = (lane >> 4) * 16;

    for (int i = tid; i < 2048; i += 128) {
        int row = i >> 5, ch = i & 31;
        uint32_t sw = (ch >> 3) * 8192 + SWZ128(row * 128 + (ch & 7) * 16);
        long g = (long)(b * Sx + m0 + row) * 3072 + h * 256 + ch * 8;
        cp16(sb + sw, qkv_hi + g);
    }
    auto fillKV = [&](int st, int t) {
        const int kb = t * 16;
        const uint32_t base = sb + OFF_KV + st * KVST;
        for (int i = tid; i < 512; i += 128) {
            int row = i >> 5, ch = i & 31;
            uint32_t sw = (ch >> 3) * 2048 + SWZ128(row * 128 + (ch & 7) * 16);
            long gk = (long)(b * Sx + kb + row) * 3072 + Hx + h * 256 + ch * 8;
            long gv = gk + Hx;
            cp16(base + sw,          qkv_hi + gk);
            cp16(base + 8192 + sw,   qkv_lo + gk);
            cp16(base + 16384 + sw,  qkv_hi + gv);
            cp16(base + 24576 + sw,  qkv_lo + gv);
        }
    };
    fillKV(0, 0);
    CP_COMMIT();

    float o[32][4];
#pragma unroll
    for (int nt = 0; nt < 32; nt++)
#pragma unroll
        for (int c = 0; c < 4; c++) o[nt][c] = 0.f;
    float m0_ = -1e30f, m1_ = -1e30f, l0_ = 0.f, l1_ = 0.f;

    for (int t = 0; t < 64; t++) {
        if (t + 1 < 64) { fillKV((t + 1) & 1, t + 1); CP_COMMIT(); cp_wait<1>(); }
        else cp_wait<0>();
        __syncthreads();
        const uint32_t base = sb + OFF_KV + (t & 1) * KVST;

        float s[2][4];
#pragma unroll
        for (int nt = 0; nt < 2; nt++)
#pragma unroll
            for (int c = 0; c < 4; c++) s[nt][c] = 0.f;
#pragma unroll
        for (int ks = 0; ks < 16; ks++) {
            uint32_t qh[4], r[4], kh[2][2], kl[2][2];
            uint32_t qa = sb + (ks >> 2) * 8192 +
                          SWZ128((wid * 16 + rA) * 128 + (ks & 3) * 32 + cA);
            ldmx4(qh, qa);
            uint32_t ka = base + (ks >> 2) * 2048 +
                          SWZ128(rB * 128 + (ks & 3) * 32 + cB);
            ldmx4(r, ka);
            kh[0][0] = r[0]; kh[0][1] = r[1]; kh[1][0] = r[2]; kh[1][1] = r[3];
            ldmx4(r, ka + 8192);
            kl[0][0] = r[0]; kl[0][1] = r[1]; kl[1][0] = r[2]; kl[1][1] = r[3];
#pragma unroll
            for (int nt = 0; nt < 2; nt++) mma_f32(s[nt], qh, kh[nt]);
#pragma unroll
            for (int nt = 0; nt < 2; nt++) mma_f32(s[nt], qh, kl[nt]);
        }

        float mx0 = -1e30f, mx1 = -1e30f;
#pragma unroll
        for (int nt = 0; nt < 2; nt++) {
            s[nt][0] *= 0.0625f; s[nt][1] *= 0.0625f;
            s[nt][2] *= 0.0625f; s[nt][3] *= 0.0625f;
            mx0 = fmaxf(mx0, fmaxf(s[nt][0], s[nt][1]));
            mx1 = fmaxf(mx1, fmaxf(s[nt][2], s[nt][3]));
        }
        mx0 = fmaxf(mx0, __shfl_xor_sync(0xffffffffu, mx0, 1));
        mx0 = fmaxf(mx0, __shfl_xor_sync(0xffffffffu, mx0, 2));
        mx1 = fmaxf(mx1, __shfl_xor_sync(0xffffffffu, mx1, 1));
        mx1 = fmaxf(mx1, __shfl_xor_sync(0xffffffffu, mx1, 2));
        float mn0 = fmaxf(m0_, mx0), mn1 = fmaxf(m1_, mx1);
        float cr0 = __expf(m0_ - mn0), cr1 = __expf(m1_ - mn1);
        m0_ = mn0; m1_ = mn1;
        float sum0 = 0.f, sum1 = 0.f;
#pragma unroll
        for (int nt = 0; nt < 2; nt++) {
            s[nt][0] = __expf(s[nt][0] - mn0); sum0 += s[nt][0];
            s[nt][1] = __expf(s[nt][1] - mn0); sum0 += s[nt][1];
            s[nt][2] = __expf(s[nt][2] - mn1); sum1 += s[nt][2];
            s[nt][3] = __expf(s[nt][3] - mn1); sum1 += s[nt][3];
        }
        sum0 += __shfl_xor_sync(0xffffffffu, sum0, 1);
        sum0 += __shfl_xor_sync(0xffffffffu, sum0, 2);
        sum1 += __shfl_xor_sync(0xffffffffu, sum1, 1);
        sum1 += __shfl_xor_sync(0xffffffffu, sum1, 2);
        l0_ = l0_ * cr0 + sum0;
        l1_ = l1_ * cr1 + sum1;
#pragma unroll
        for (int nt = 0; nt < 32; nt++) {
            o[nt][0] *= cr0; o[nt][1] *= cr0;
            o[nt][2] *= cr1; o[nt][3] *= cr1;
        }

        uint32_t pah[4];
        pah[0] = pack_h2(s[0][0], s[0][1]);
        pah[1] = pack_h2(s[0][2], s[0][3]);
        pah[2] = pack_h2(s[1][0], s[1][1]);
        pah[3] = pack_h2(s[1][2], s[1][3]);
#pragma unroll
        for (int n2 = 0; n2 < 16; n2++) {
            uint32_t r[4], vh0[2], vh1[2], vl0[2], vl1[2];
            uint32_t va = base + 16384 + (n2 >> 2) * 2048 +
                          SWZ128(rV * 128 + (n2 & 3) * 32 + cV);
            ldmx4t(r, va);
            vh0[0] = r[0]; vh0[1] = r[1]; vh1[0] = r[2]; vh1[1] = r[3];
            ldmx4t(r, va + 8192);
            vl0[0] = r[0]; vl0[1] = r[1]; vl1[0] = r[2]; vl1[1] = r[3];
            mma_f32(o[2*n2],   pah, vh0);
            mma_f32(o[2*n2+1], pah, vh1);
            mma_f32(o[2*n2],   pah, vl0);
            mma_f32(o[2*n2+1], pah, vl1);
        }
        __syncthreads();
    }

    float inv0 = 1.f / l0_, inv1 = 1.f / l1_;
    const long row0 = (long)(b * Sx + m0 + wid * 16 + gid) * Hx + h * 256;
    const long row1 = row0 + 8 * Hx;
#pragma unroll
    for (int nt = 0; nt < 32; nt++) {
        int d = nt * 8 + tig * 2;
        *(__half2*)(chi + row0 + d) = __halves2half2(
            __float2half(o[nt][0] * inv0), __float2half(o[nt][1] * inv0));
        *(__half2*)(chi + row1 + d) = __halves2half2(
            __float2half(o[nt][2] * inv1), __float2half(o[nt][3] * inv1));
    }
}

// ---------------------------------------------------------------------------
// conversions
// ---------------------------------------------------------------------------
struct WPack {
    const float* src[8];
    __half* dhi[8];
    __half* dlo[8];
    int N[8];
    int tileOff[9];
};

__global__ void wsplit_all(WPack p)
{
    __shared__ float t[32][33];
    int bid = blockIdx.x;
    int w = 0;
    while (bid >= p.tileOff[w + 1]) w++;
    int tt = bid - p.tileOff[w];
    int ntx = p.N[w] >> 5;
    int n0 = (tt % ntx) * 32, k0 = (tt / ntx) * 32;
    const float* src = p.src[w];
    __half* hi = p.dhi[w];
    __half* lo = p.dlo[w];
    int N = p.N[w];
    int tx = threadIdx.x, ty = threadIdx.y;
    for (int j = ty; j < 32; j += 8)
        t[j][tx] = src[(long)(k0 + j) * N + n0 + tx];
    __syncthreads();
    for (int j = ty; j < 32; j += 8) {
        float v = t[tx][j];
        long o = (long)(n0 + j) * 1024 + k0 + tx;
        __half h = __float2half(v);
        hi[o] = h;
        lo[o] = __float2half(v - __half2float(h));
    }
}

__global__ void bcat_k(const float* __restrict__ bq, const float* __restrict__ bk,
                       const float* __restrict__ bv, float* __restrict__ dst)
{
    int i = blockIdx.x * 256 + threadIdx.x;
    if (i < 1024) dst[i] = bq[i];
    else if (i < 2048) dst[i] = bk[i - 1024];
    else if (i < 3072) dst[i] = bv[i - 2048];
}

// Fused: per row — xs_hi conversion + mod gate (amvec computed in-block)
__global__ void mod_k(const float* __restrict__ X, const float* __restrict__ cgW,
                      const float* __restrict__ cons, const float* __restrict__ amW,
                      const float* __restrict__ amb, const float* __restrict__ cgb,
                      __half* __restrict__ xs_hi, float* __restrict__ mod)
{
    __shared__ float xs[Hx];
    __shared__ float part[8][NHx];
    __shared__ float amv_s[NHx];
    int row = blockIdx.x;
    const float* x = X + (long)row * Hx;
    if (threadIdx.x < NHx) {
        int n = threadIdx.x;
        float s = amb[n] + cgb[n];
#pragma unroll
        for (int k = 0; k < 16; k++) s += cons[k] * amW[k * NHx + n];
        amv_s[n] = s;
    }
    for (int i = threadIdx.x; i < Hx; i += 128) {
        float v = x[i];
        xs[i] = v;
        xs_hi[(long)row * Hx + i] = __float2half(v);
    }
    __syncthreads();
    int n = threadIdx.x & 15;
    int g = threadIdx.x >> 4;
    float s = 0.f;
    for (int k = g; k < Hx; k += 8) s += xs[k] * cgW[k * NHx + n];
    part[g][n] = s;
    __syncthreads();
    if (threadIdx.x < NHx) {
        float t = amv_s[threadIdx.x];
#pragma unroll
        for (int gg = 0; gg < 8; gg++) t += part[gg][threadIdx.x];
        mod[(long)row * NHx + threadIdx.x] = 1.f / (1.f + __expf(-t));
    }
}

// ---------------------------------------------------------------------------
// Host side
// ---------------------------------------------------------------------------
template<typename T>
static T* symaddr(const void* sym) {
    void* p = nullptr;
    cudaGetSymbolAddress(&p, sym);
    return (T*)p;
}
typedef __half hf;

extern "C" void kernel_launch(void* const* d_in, const int* in_sizes, int n_in,
                              void* d_out, int out_size)
{
    (void)in_sizes; (void)n_in; (void)out_size;
    const float* X      = (const float*)d_in[0];
    const float* cons   = (const float*)d_in[1];
    const float* Wq     = (const float*)d_in[2];
    const float* bq     = (const float*)d_in[3];
    const float* Wk     = (const float*)d_in[4];
    const float* bk     = (const float*)d_in[5];
    const float* Wv     = (const float*)d_in[6];
    const float* bv     = (const float*)d_in[7];
    const float* cgW    = (const float*)d_in[8];
    const float* cgb    = (const float*)d_in[9];
    const float* amW    = (const float*)d_in[10];
    const float* amb    = (const float*)d_in[11];
    const float* caWin  = (const float*)d_in[12];
    const float* cabin  = (const float*)d_in[13];
    const float* caWout = (const float*)d_in[14];
    const float* cabout = (const float*)d_in[15];
    const float* mcWin  = (const float*)d_in[16];
    const float* mcbin  = (const float*)d_in[17];
    const float* mcWout = (const float*)d_in[18];
    const float* mcbout = (const float*)d_in[19];
    const float* Wo     = (const float*)d_in[20];
    const float* bo     = (const float*)d_in[21];
    float* out = (float*)d_out;

    hf *xs_hi = symaddr<hf>(g_xs_hi);
    hf *wqkvT_hi = symaddr<hf>(g_wqkvT_hi), *wqkvT_lo = symaddr<hf>(g_wqkvT_lo);
    hf *caWinT_hi = symaddr<hf>(g_caWinT_hi), *caWinT_lo = symaddr<hf>(g_caWinT_lo);
    hf *caWoutT_hi = symaddr<hf>(g_caWoutT_hi), *caWoutT_lo = symaddr<hf>(g_caWoutT_lo);
    hf *mcWinT_hi = symaddr<hf>(g_mcWinT_hi), *mcWinT_lo = symaddr<hf>(g_mcWinT_lo);
    hf *mcWoutT_hi = symaddr<hf>(g_mcWoutT_hi), *mcWoutT_lo = symaddr<hf>(g_mcWoutT_lo);
    hf *woT_hi = symaddr<hf>(g_woT_hi), *woT_lo = symaddr<hf>(g_woT_lo);
    hf *qk_hi = symaddr<hf>(g_qk_hi), *qk_lo = symaddr<hf>(g_qk_lo);
    hf *vT_hi = symaddr<hf>(g_vT_hi), *vT_lo = symaddr<hf>(g_vT_lo);
    hf *qkv_hi = symaddr<hf>(g_qkv_hi), *qkv_lo = symaddr<hf>(g_qkv_lo);
    hf *ctx2_hi = symaddr<hf>(g_ctx2_hi);
    hf *ctxb_hi = symaddr<hf>(g_ctxb_hi);
    hf *ctxm_hi = symaddr<hf>(g_ctxm_hi);
    float *ctx = symaddr<float>(g_ctx), *ctxb = symaddr<float>(g_ctxb);
    float *mod = symaddr<float>(g_mod);
    float *bqkv = symaddr<float>(g_bqkv);

    const int SMG  = 2 * 49152;          // 98304, 2 CTAs/SM
    const int SMFA = 16384 + 2 * 32768;  // 81920
    const int SMFB = 32768 + 2 * 32768;  // 98304, 2 CTAs/SM
    cudaFuncSetAttribute(gemm128,      cudaFuncAttributeMaxDynamicSharedMemorySize, SMG);
    cudaFuncSetAttribute(flash_main,   cudaFuncAttributeMaxDynamicSharedMemorySize, SMFA);
    cudaFuncSetAttribute(flash_branch, cudaFuncAttributeMaxDynamicSharedMemorySize, SMFB);

    const long SH = (long)Sx * Hx;
    dim3 tb(32, 8);
    dim3 gProj(Hx/128, MB/128, 1);       // 8 x 32 = 256 CTAs
    dim3 gQKV(3*Hx/128, MB/128, 1);      // 24 x 32 = 768 CTAs

    WPack wp;
    wp.src[0] = Wq;     wp.dhi[0] = wqkvT_hi;               wp.dlo[0] = wqkvT_lo;               wp.N[0] = Hx;
    wp.src[1] = Wk;     wp.dhi[1] = wqkvT_hi + Hx * Hx;     wp.dlo[1] = wqkvT_lo + Hx * Hx;     wp.N[1] = Hx;
    wp.src[2] = Wv;     wp.dhi[2] = wqkvT_hi + 2 * Hx * Hx; wp.dlo[2] = wqkvT_lo + 2 * Hx * Hx; wp.N[2] = Hx;
    wp.src[3] = caWin;  wp.dhi[3] = caWinT_hi;  wp.dlo[3] = caWinT_lo;  wp.N[3] = 3 * Hx;
    wp.src[4] = caWout; wp.dhi[4] = caWoutT_hi; wp.dlo[4] = caWoutT_lo; wp.N[4] = Hx;
    wp.src[5] = mcWin;  wp.dhi[5] = mcWinT_hi;  wp.dlo[5] = mcWinT_lo;  wp.N[5] = 3 * Hx;
    wp.src[6] = mcWout; wp.dhi[6] = mcWoutT_hi; wp.dlo[6] = mcWoutT_lo; wp.N[6] = Hx;
    wp.src[7] = Wo;     wp.dhi[7] = woT_hi;     wp.dlo[7] = woT_lo;     wp.N[7] = Hx;
    wp.tileOff[0] = 0;
    for (int i = 0; i < 8; i++)
        wp.tileOff[i + 1] = wp.tileOff[i] + (wp.N[i] / 32) * (Hx / 32);

    // prep
    bcat_k<<<12, 256>>>(bq, bk, bv, bqkv);                                  // 0
    wsplit_all<<<wp.tileOff[8], tb>>>(wp);                                  // 1
    mod_k<<<MB, 128>>>(X, cgW, cons, amW, amb, cgb, xs_hi, mod);            // 2

    // 3: merged QKV projection
    gemm128<<<gQKV, 256, SMG>>>(xs_hi, Hx, 0, 0,
        wqkvT_hi, wqkvT_lo, Hx, 0, 0,
        nullptr, qk_hi, qk_lo, 2 * Hx, 0, 0,
        vT_hi, vT_lo, 2 * Hx, 3 * Hx, SH,
        Hx, 1, bqkv, 1.f, nullptr, 0, 0.f);

    // 4: fused main attention -> ctx (fp32)
    flash_main<<<dim3(Sx/128, Bx * NHx), 256, SMFA>>>(
        qk_hi, qk_lo, vT_hi, vT_lo, mod, ctx);

    // ---- causal + meta branches ----
    for (int br = 0; br < 2; br++) {
        const hf* winT_hi = br ? mcWinT_hi : caWinT_hi;
        const hf* winT_lo = br ? mcWinT_lo : caWinT_lo;
        const hf* woutT_hi = br ? mcWoutT_hi : caWoutT_hi;
        const hf* woutT_lo = br ? mcWoutT_lo : caWoutT_lo;
        const float* bin  = br ? mcbin  : cabin;
        const float* bout = br ? mcbout : cabout;
        const hf* a_hi = br ? ctxb_hi : xs_hi;

        // in-proj: qkv = A @ Win + bin (split fp16 out)
        gemm128<<<gQKV, 256, SMG>>>(a_hi, Hx, 0, 0,
            winT_hi, winT_lo, Hx, 0, 0,
            nullptr, qkv_hi, qkv_lo, 3 * Hx, 0, 0,
            nullptr, nullptr, 0, 0, 0,
            Hx, 1, bin, 1.f, nullptr, 0, 0.f);
        // fused branch attention -> ctx2 (fp16 hi only)
        flash_branch<<<dim3(Sx/64, Bx * BR_HEADS), 128, SMFB>>>(
            qkv_hi, qkv_lo, ctx2_hi);
        // out-proj + blend
        if (br == 0) {
            gemm128<<<gProj, 256, SMG>>>(ctx2_hi, Hx, 0, 0,
                woutT_hi, woutT_lo, Hx, 0, 0,
                ctxb, ctxb_hi, nullptr, Hx, 0, 0,
                nullptr, nullptr, 0, 0, 0,
                Hx, 1, bout, CAUSAL_W, ctx, Hx, 1.f - CAUSAL_W);
        } else {
            gemm128<<<gProj, 256, SMG>>>(ctx2_hi, Hx, 0, 0,
                woutT_hi, woutT_lo, Hx, 0, 0,
                nullptr, ctxm_hi, nullptr, Hx, 0, 0,
                nullptr, nullptr, 0, 0, 0,
                Hx, 1, bout, META_W, ctxb, Hx, 1.f - META_W);
        }
    }

    // ---- final projection ----
    gemm128<<<gProj, 256, SMG>>>(ctxm_hi, Hx, 0, 0,
        woT_hi, woT_lo, Hx, 0, 0,
        out, nullptr, nullptr, Hx, 0, 0,
        nullptr, nullptr, 0, 0, 0,
        Hx, 1, bo, 1.f, nullptr, 0, 0.f);
}

// round 15
// speedup vs baseline: 1.2174x; 1.2174x over previous
#include <cuda_runtime.h>
#include <cuda_fp16.h>
#include <cstdint>
#include <math.h>

#define Bx 4
#define Sx 1024
#define Hx 1024
#define NHx 16
#define HDx 64
#define BR_HEADS 4
#define BR_HD 256
static const float CAUSAL_W = 0.7f;
static const float META_W  = 0.15f;

#define MB (Bx * Sx)   // 4096 rows

// ---------------------------------------------------------------------------
// Device scratch (fp16; weights hi-only now)
// ---------------------------------------------------------------------------
__device__ __half g_xs_hi[MB * Hx];
__device__ __half g_wqkvT_hi[3 * Hx * Hx];
__device__ __half g_caWinT_hi[3 * Hx * Hx];
__device__ __half g_caWoutT_hi[Hx * Hx];
__device__ __half g_mcWinT_hi[3 * Hx * Hx];
__device__ __half g_mcWoutT_hi[Hx * Hx];
__device__ __half g_woT_hi[Hx * Hx];
__device__ float  g_bqkv[3 * Hx];

__device__ __half g_qk_hi[MB * 2 * Hx], g_qk_lo[MB * 2 * Hx];   // [m][q(1024) k(1024)]
__device__ __half g_vT_hi[MB * Hx], g_vT_lo[MB * Hx];           // [b][d][s]
__device__ __half g_qkv_hi[MB * 3 * Hx], g_qkv_lo[MB * 3 * Hx];

__device__ float g_ctx [MB * Hx];
__device__ float g_ctxb[MB * Hx];
__device__ __half g_ctx2_hi[MB * Hx];
__device__ __half g_ctxb_hi[MB * Hx];
__device__ __half g_ctxm_hi[MB * Hx];
__device__ float g_mod[MB * NHx];

// ---------------------------------------------------------------------------
// PTX helpers
// ---------------------------------------------------------------------------
__device__ __forceinline__ uint32_t smem_u32(const void* p) {
    uint32_t a;
    asm("{ .reg .u64 t; cvta.to.shared.u64 t, %1; cvt.u32.u64 %0, t; }" : "=r"(a) : "l"(p));
    return a;
}
#define SWZ128(o) ((o) ^ (((o) >> 3) & 0x70))

__device__ __forceinline__ void cp16(uint32_t s, const void* g) {
    asm volatile("cp.async.cg.shared.global [%0], [%1], 16;"
                 :: "r"(s), "l"(__cvta_generic_to_global(g)) : "memory");
}
#define CP_COMMIT() asm volatile("cp.async.commit_group;" ::: "memory")
template<int N> __device__ __forceinline__ void cp_wait() {
    asm volatile("cp.async.wait_group %0;" :: "n"(N) : "memory");
}
__device__ __forceinline__ void ldmx4(uint32_t* r, uint32_t a) {
    asm volatile("ldmatrix.sync.aligned.m8n8.x4.shared.b16 {%0,%1,%2,%3}, [%4];"
        : "=r"(r[0]), "=r"(r[1]), "=r"(r[2]), "=r"(r[3]) : "r"(a));
}
__device__ __forceinline__ void ldmx4t(uint32_t* r, uint32_t a) {
    asm volatile("ldmatrix.sync.aligned.m8n8.x4.trans.shared.b16 {%0,%1,%2,%3}, [%4];"
        : "=r"(r[0]), "=r"(r[1]), "=r"(r[2]), "=r"(r[3]) : "r"(a));
}
__device__ __forceinline__ void mma_f32(float* c, const uint32_t* a, const uint32_t* b) {
    asm volatile(
        "mma.sync.aligned.m16n8k16.row.col.f32.f16.f16.f32 "
        "{%0,%1,%2,%3}, {%4,%5,%6,%7}, {%8,%9}, {%0,%1,%2,%3};"
        : "+f"(c[0]), "+f"(c[1]), "+f"(c[2]), "+f"(c[3])
        : "r"(a[0]), "r"(a[1]), "r"(a[2]), "r"(a[3]), "r"(b[0]), "r"(b[1]));
}
__device__ __forceinline__ uint32_t pack_h2(float x, float y) {
    uint32_t r;
    asm("cvt.rn.f16x2.f32 %0, %1, %2;" : "=r"(r) : "f"(y), "f"(x));
    return r;
}

// ---------------------------------------------------------------------------
// 1-term fp16 GEMM: C = alpha*(Ah @ Bh^T + bias) + beta*blend.
// BM=128 x BN=64, BK=64, 8 warps (4m x 2n, warp 32x32), 2-stage cp.async.
// Stage: A 16K | B 8K = 24K (x2 = 48K) -> 2 CTAs/SM.
// Outputs: Cf (f32) / Chi (+optional Clo) split fp16 / Thi,Tlo transposed.
// ---------------------------------------------------------------------------
__global__ void __launch_bounds__(256, 2) gemm64(
    const __half* __restrict__ Ah, int lda, long sA1, long sA2,
    const __half* __restrict__ Bh, int ldb, long sB1, long sB2,
    float* Cf, __half* Chi, __half* Clo,
    int ldc, long sC1, long sC2,
    __half* Thi, __half* Tlo, int tn0, int tn1, long TB,
    int K, int Z2,
    const float* __restrict__ bias, float alpha,
    const float* __restrict__ blend, int ldbl, float beta)
{
    constexpr int BSTG = 24576;
    extern __shared__ char dsm[];
    uint32_t sb = smem_u32(dsm);

    const int z = blockIdx.z, z1 = z / Z2, z2 = z % Z2;
    {
        Ah += z1 * sA1 + z2 * sA2;
        Bh += z1 * sB1 + z2 * sB2;
        long co = z1 * sC1 + z2 * sC2;
        if (Cf)  Cf  += co;
        if (Chi) Chi += co;
        if (Clo) Clo += co;
    }

    const int tid = threadIdx.x, lane = tid & 31, wid = tid >> 5;
    const int wm = wid >> 1, wn = wid & 1;
    const int m0 = blockIdx.y * 128, n0 = blockIdx.x * 64;

    float acc[2][4][4];
#pragma unroll
    for (int a = 0; a < 2; a++)
#pragma unroll
        for (int b = 0; b < 4; b++)
#pragma unroll
            for (int cc = 0; cc < 4; cc++) acc[a][b][cc] = 0.f;

    const int nk = K >> 6;

    auto fill = [&](int st, int c) {
        const int k0 = c << 6;
        const uint32_t base = sb + st * BSTG;
        for (int i = tid; i < 1024; i += 256) {       // A: 128 rows x 8 groups
            int row = i >> 3, gb = (i & 7) * 16;
            uint32_t sw = SWZ128(row * 128 + gb);
            cp16(base + sw, Ah + (long)(m0 + row) * lda + k0 + (gb >> 1));
        }
        for (int i = tid; i < 512; i += 256) {        // B: 64 rows x 8 groups
            int row = i >> 3, gb = (i & 7) * 16;
            uint32_t sw = SWZ128(row * 128 + gb);
            cp16(base + 16384 + sw, Bh + (long)(n0 + row) * ldb + k0 + (gb >> 1));
        }
    };

    const int rA = (lane & 7) + ((lane >> 3) & 1) * 8;
    const int cA = ((lane >> 4) & 1) * 16;
    const int rB = (lane & 7) + ((lane >> 4) & 1) * 8;
    const int cB = ((lane >> 3) & 1) * 16;

    fill(0, 0); CP_COMMIT();
    for (int c = 0; c < nk; c++) {
        if (c + 1 < nk) { fill((c + 1) & 1, c + 1); CP_COMMIT(); cp_wait<1>(); }
        else cp_wait<0>();
        __syncthreads();
        const uint32_t base = sb + (c & 1) * BSTG;
#pragma unroll
        for (int ks = 0; ks < 4; ks++) {
            uint32_t bh[4][2];
#pragma unroll
            for (int n2 = 0; n2 < 2; n2++) {
                uint32_t r[4];
                uint32_t bd = base + 16384 + SWZ128((wn * 32 + n2 * 16 + rB) * 128 + ks * 32 + cB);
                ldmx4(r, bd);
                bh[2*n2][0] = r[0]; bh[2*n2][1] = r[1];
                bh[2*n2+1][0] = r[2]; bh[2*n2+1][1] = r[3];
            }
            uint32_t ah[2][4];
#pragma unroll
            for (int mt = 0; mt < 2; mt++) {
                uint32_t ad = base + SWZ128((wm * 32 + mt * 16 + rA) * 128 + ks * 32 + cA);
                ldmx4(ah[mt], ad);
            }
#pragma unroll
            for (int mt = 0; mt < 2; mt++)
#pragma unroll
                for (int nt = 0; nt < 4; nt++)
                    mma_f32(acc[mt][nt], ah[mt], bh[nt]);
        }
        __syncthreads();
    }

    const int gid = lane >> 2, tig = lane & 3;
    auto store2 = [&](int m, int n, float v0, float v1) {
        if (bias) { v0 += bias[n]; v1 += bias[n + 1]; }
        v0 *= alpha; v1 *= alpha;
        if (blend) {
            const float* bp = blend + (long)m * ldbl + n;
            v0 += beta * bp[0]; v1 += beta * bp[1];
        }
        if (Cf) *(float2*)(Cf + (long)m * ldc + n) = make_float2(v0, v1);
        if (Chi && (!Thi || n < tn0)) {
            __half h0 = __float2half(v0), h1 = __float2half(v1);
            long o = (long)m * ldc + n;
            *(__half2*)(Chi + o) = __halves2half2(h0, h1);
            if (Clo)
                *(__half2*)(Clo + o) = __halves2half2(
                    __float2half(v0 - __half2float(h0)), __float2half(v1 - __half2float(h1)));
        }
        if (Thi && n >= tn0 && n < tn1) {
            __half h0 = __float2half(v0), h1 = __float2half(v1);
            long o = (long)(m >> 10) * TB + (long)(n - tn0) * 1024 + (m & 1023);
            Thi[o] = h0;        Tlo[o] = __float2half(v0 - __half2float(h0));
            Thi[o + 1024] = h1; Tlo[o + 1024] = __float2half(v1 - __half2float(h1));
        }
    };
#pragma unroll
    for (int mt = 0; mt < 2; mt++)
#pragma unroll
        for (int nt = 0; nt < 4; nt++) {
            int m = m0 + wm * 32 + mt * 16 + gid;
            int n = n0 + wn * 32 + nt * 8 + tig * 2;
            store2(m,     n, acc[mt][nt][0], acc[mt][nt][1]);
            store2(m + 8, n, acc[mt][nt][2], acc[mt][nt][3]);
        }
}

// ---------------------------------------------------------------------------
// Flash attention, main branch (HD=64, mod-gated, 2-term).  (as R13)
// ---------------------------------------------------------------------------
__global__ void __launch_bounds__(256) flash_main(
    const __half* __restrict__ qk_hi, const __half* __restrict__ qk_lo,
    const __half* __restrict__ vth_g, const __half* __restrict__ vtl_g,
    const float* __restrict__ mod, float* __restrict__ ctx)
{
    constexpr int OFF_KV = 16384, KVST = 32768;
    extern __shared__ char dsm[];
    uint32_t sb = smem_u32(dsm);

    const int z = blockIdx.y, b = z >> 4, h = z & 15;
    const int m0 = blockIdx.x * 128;
    const int tid = threadIdx.x, lane = tid & 31, wid = tid >> 5;
    const int gid = lane >> 2, tig = lane & 3;
    const long SHl = (long)Sx * Hx;

    const int rA = (lane & 7) + ((lane >> 3) & 1) * 8;
    const int cA = ((lane >> 4) & 1) * 16;
    const int rB = (lane & 7) + ((lane >> 4) & 1) * 8;
    const int cB = ((lane >> 3) & 1) * 16;

    for (int i = tid; i < 1024; i += 256) {
        int row = i >> 3, ch = i & 7;
        uint32_t sw = SWZ128(row * 128 + ch * 16);
        long go = (long)(b * Sx + m0 + row) * 2048 + h * 64 + ch * 8;
        cp16(sb + sw, qk_hi + go);
    }
    auto fillKV = [&](int st, int t) {
        const int kb = t * 64;
        const uint32_t base = sb + OFF_KV + st * KVST;
        for (int i = tid; i < 512; i += 256) {
            int row = i >> 3, ch = i & 7;
            uint32_t sw = SWZ128(row * 128 + ch * 16);
            long gk = (long)(b * Sx + kb + row) * 2048 + 1024 + h * 64 + ch * 8;
            long gv = (long)b * SHl + (long)(h * 64 + row) * Sx + kb + ch * 8;
            cp16(base + sw,          qk_hi + gk);
            cp16(base + 8192 + sw,   qk_lo + gk);
            cp16(base + 16384 + sw,  vth_g + gv);
            cp16(base + 24576 + sw,  vtl_g + gv);
        }
    };
    fillKV(0, 0);
    CP_COMMIT();

    const int r0 = m0 + wid * 16 + gid;
    const float msc0 = 0.125f * mod[(long)(b * Sx + r0) * NHx + h];
    const float msc1 = 0.125f * mod[(long)(b * Sx + r0 + 8) * NHx + h];

    uint32_t qh[4][4];
    float o[8][4];
#pragma unroll
    for (int nt = 0; nt < 8; nt++)
#pragma unroll
        for (int c = 0; c < 4; c++) o[nt][c] = 0.f;
    float m0_ = -1e30f, m1_ = -1e30f, l0_ = 0.f, l1_ = 0.f;

    const int NTILE = Sx / 64;
    for (int t = 0; t < NTILE; t++) {
        if (t + 1 < NTILE) { fillKV((t + 1) & 1, t + 1); CP_COMMIT(); cp_wait<1>(); }
        else cp_wait<0>();
        __syncthreads();
        const uint32_t base = sb + OFF_KV + (t & 1) * KVST;

        if (t == 0) {
#pragma unroll
            for (int ks = 0; ks < 4; ks++) {
                uint32_t ad = sb + SWZ128((wid * 16 + rA) * 128 + ks * 32 + cA);
                ldmx4(qh[ks], ad);
            }
        }

        float s[8][4];
#pragma unroll
        for (int nt = 0; nt < 8; nt++)
#pragma unroll
            for (int c = 0; c < 4; c++) s[nt][c] = 0.f;
#pragma unroll
        for (int ks = 0; ks < 4; ks++) {
            uint32_t bh[8][2], bl[8][2];
#pragma unroll
            for (int n2 = 0; n2 < 4; n2++) {
                uint32_t r[4];
                uint32_t bd = base + SWZ128((n2 * 16 + rB) * 128 + ks * 32 + cB);
                ldmx4(r, bd);
                bh[2*n2][0] = r[0]; bh[2*n2][1] = r[1];
                bh[2*n2+1][0] = r[2]; bh[2*n2+1][1] = r[3];
                ldmx4(r, bd + 8192);
                bl[2*n2][0] = r[0]; bl[2*n2][1] = r[1];
                bl[2*n2+1][0] = r[2]; bl[2*n2+1][1] = r[3];
            }
#pragma unroll
            for (int nt = 0; nt < 8; nt++) mma_f32(s[nt], qh[ks], bh[nt]);
#pragma unroll
            for (int nt = 0; nt < 8; nt++) mma_f32(s[nt], qh[ks], bl[nt]);
        }

        float mx0 = -1e30f, mx1 = -1e30f;
#pragma unroll
        for (int nt = 0; nt < 8; nt++) {
            s[nt][0] *= msc0; s[nt][1] *= msc0;
            s[nt][2] *= msc1; s[nt][3] *= msc1;
            mx0 = fmaxf(mx0, fmaxf(s[nt][0], s[nt][1]));
            mx1 = fmaxf(mx1, fmaxf(s[nt][2], s[nt][3]));
        }
        mx0 = fmaxf(mx0, __shfl_xor_sync(0xffffffffu, mx0, 1));
        mx0 = fmaxf(mx0, __shfl_xor_sync(0xffffffffu, mx0, 2));
        mx1 = fmaxf(mx1, __shfl_xor_sync(0xffffffffu, mx1, 1));
        mx1 = fmaxf(mx1, __shfl_xor_sync(0xffffffffu, mx1, 2));
        float mn0 = fmaxf(m0_, mx0), mn1 = fmaxf(m1_, mx1);
        float cr0 = __expf(m0_ - mn0), cr1 = __expf(m1_ - mn1);
        m0_ = mn0; m1_ = mn1;
        float sum0 = 0.f, sum1 = 0.f;
#pragma unroll
        for (int nt = 0; nt < 8; nt++) {
            s[nt][0] = __expf(s[nt][0] - mn0); sum0 += s[nt][0];
            s[nt][1] = __expf(s[nt][1] - mn0); sum0 += s[nt][1];
            s[nt][2] = __expf(s[nt][2] - mn1); sum1 += s[nt][2];
            s[nt][3] = __expf(s[nt][3] - mn1); sum1 += s[nt][3];
        }
        sum0 += __shfl_xor_sync(0xffffffffu, sum0, 1);
        sum0 += __shfl_xor_sync(0xffffffffu, sum0, 2);
        sum1 += __shfl_xor_sync(0xffffffffu, sum1, 1);
        sum1 += __shfl_xor_sync(0xffffffffu, sum1, 2);
        l0_ = l0_ * cr0 + sum0;
        l1_ = l1_ * cr1 + sum1;
#pragma unroll
        for (int nt = 0; nt < 8; nt++) {
            o[nt][0] *= cr0; o[nt][1] *= cr0;
            o[nt][2] *= cr1; o[nt][3] *= cr1;
        }

#pragma unroll
        for (int j = 0; j < 4; j++) {
            uint32_t pah[4];
            pah[0] = pack_h2(s[2*j][0],   s[2*j][1]);
            pah[1] = pack_h2(s[2*j][2],   s[2*j][3]);
            pah[2] = pack_h2(s[2*j+1][0], s[2*j+1][1]);
            pah[3] = pack_h2(s[2*j+1][2], s[2*j+1][3]);
            uint32_t vh[8][2], vl[8][2];
#pragma unroll
            for (int n2 = 0; n2 < 4; n2++) {
                uint32_t r[4];
                uint32_t bd = base + 16384 + SWZ128((n2 * 16 + rB) * 128 + j * 32 + cB);
                ldmx4(r, bd);
                vh[2*n2][0] = r[0]; vh[2*n2][1] = r[1];
                vh[2*n2+1][0] = r[2]; vh[2*n2+1][1] = r[3];
                ldmx4(r, bd + 8192);
                vl[2*n2][0] = r[0]; vl[2*n2][1] = r[1];
                vl[2*n2+1][0] = r[2]; vl[2*n2+1][1] = r[3];
            }
#pragma unroll
            for (int nt = 0; nt < 8; nt++) mma_f32(o[nt], pah, vh[nt]);
#pragma unroll
            for (int nt = 0; nt < 8; nt++) mma_f32(o[nt], pah, vl[nt]);
        }
        __syncthreads();
    }

    float inv0 = 1.f / l0_, inv1 = 1.f / l1_;
    const long row0 = (long)(b * Sx + r0) * Hx + h * 64;
    const long row1 = (long)(b * Sx + r0 + 8) * Hx + h * 64;
#pragma unroll
    for (int nt = 0; nt < 8; nt++) {
        int d = nt * 8 + tig * 2;
        *(float2*)(ctx + row0 + d) = make_float2(o[nt][0] * inv0, o[nt][1] * inv0);
        *(float2*)(ctx + row1 + d) = make_float2(o[nt][2] * inv1, o[nt][3] * inv1);
    }
}

// ---------------------------------------------------------------------------
// Flash attention, branch (HD=256, 4 heads, scale 1/16).  2-term,
// double-buffered KV.  (as R13)
// ---------------------------------------------------------------------------
__global__ void __launch_bounds__(128, 2) flash_branch(
    const __half* __restrict__ qkv_hi, const __half* __restrict__ qkv_lo,
    __half* __restrict__ chi)
{
    constexpr int OFF_KV = 32768, KVST = 32768;
    extern __shared__ char dsm[];
    uint32_t sb = smem_u32(dsm);

    const int b = blockIdx.y >> 2, h = blockIdx.y & 3;
    const int m0 = blockIdx.x * 64;
    const int tid = threadIdx.x, lane = tid & 31, wid = tid >> 5;
    const int gid = lane >> 2, tig = lane & 3;

    const int rA = (lane & 7) + ((lane >> 3) & 1) * 8;
    const int cA = ((lane >> 4) & 1) * 16;
    const int rB = (lane & 7) + ((lane >> 4) & 1) * 8;
    const int cB = ((lane >> 3) & 1) * 16;
    const int rV = lane & 15, cV = (lane >> 4) * 16;

    for (int i = tid; i < 2048; i += 128) {
        int row = i >> 5, ch = i & 31;
        uint32_t sw = (ch >> 3) * 8192 + SWZ128(row * 128 + (ch & 7) * 16);
        long g = (long)(b * Sx + m0 + row) * 3072 + h * 256 + ch * 8;
        cp16(sb + sw, qkv_hi + g);
    }
    auto fillKV = [&](int st, int t) {
        const int kb = t * 16;
        const uint32_t base = sb + OFF_KV + st * KVST;
        for (int i = tid; i < 512; i += 128) {
            int row = i >> 5, ch = i & 31;
            uint32_t sw = (ch >> 3) * 2048 + SWZ128(row * 128 + (ch & 7) * 16);
            long gk = (long)(b * Sx + kb + row) * 3072 + Hx + h * 256 + ch * 8;
            long gv = gk + Hx;
            cp16(base + sw,          qkv_hi + gk);
            cp16(base + 8192 + sw,   qkv_lo + gk);
            cp16(base + 16384 + sw,  qkv_hi + gv);
            cp16(base + 24576 + sw,  qkv_lo + gv);
        }
    };
    fillKV(0, 0);
    CP_COMMIT();

    float o[32][4];
#pragma unroll
    for (int nt = 0; nt < 32; nt++)
#pragma unroll
        for (int c = 0; c < 4; c++) o[nt][c] = 0.f;
    float m0_ = -1e30f, m1_ = -1e30f, l0_ = 0.f, l1_ = 0.f;

    for (int t = 0; t < 64; t++) {
        if (t + 1 < 64) { fillKV((t + 1) & 1, t + 1); CP_COMMIT(); cp_wait<1>(); }
        else cp_wait<0>();
        __syncthreads();
        const uint32_t base = sb + OFF_KV + (t & 1) * KVST;

        float s[2][4];
#pragma unroll
        for (int nt = 0; nt < 2; nt++)
#pragma unroll
            for (int c = 0; c < 4; c++) s[nt][c] = 0.f;
#pragma unroll
        for (int ks = 0; ks < 16; ks++) {
            uint32_t qh[4], r[4], kh[2][2], kl[2][2];
            uint32_t qa = sb + (ks >> 2) * 8192 +
                          SWZ128((wid * 16 + rA) * 128 + (ks & 3) * 32 + cA);
            ldmx4(qh, qa);
            uint32_t ka = base + (ks >> 2) * 2048 +
                          SWZ128(rB * 128 + (ks & 3) * 32 + cB);
            ldmx4(r, ka);
            kh[0][0] = r[0]; kh[0][1] = r[1]; kh[1][0] = r[2]; kh[1][1] = r[3];
            ldmx4(r, ka + 8192);
            kl[0][0] = r[0]; kl[0][1] = r[1]; kl[1][0] = r[2]; kl[1][1] = r[3];
#pragma unroll
            for (int nt = 0; nt < 2; nt++) mma_f32(s[nt], qh, kh[nt]);
#pragma unroll
            for (int nt = 0; nt < 2; nt++) mma_f32(s[nt], qh, kl[nt]);
        }

        float mx0 = -1e30f, mx1 = -1e30f;
#pragma unroll
        for (int nt = 0; nt < 2; nt++) {
            s[nt][0] *= 0.0625f; s[nt][1] *= 0.0625f;
            s[nt][2] *= 0.0625f; s[nt][3] *= 0.0625f;
            mx0 = fmaxf(mx0, fmaxf(s[nt][0], s[nt][1]));
            mx1 = fmaxf(mx1, fmaxf(s[nt][2], s[nt][3]));
        }
        mx0 = fmaxf(mx0, __shfl_xor_sync(0xffffffffu, mx0, 1));
        mx0 = fmaxf(mx0, __shfl_xor_sync(0xffffffffu, mx0, 2));
        mx1 = fmaxf(mx1, __shfl_xor_sync(0xffffffffu, mx1, 1));
        mx1 = fmaxf(mx1, __shfl_xor_sync(0xffffffffu, mx1, 2));
        float mn0 = fmaxf(m0_, mx0), mn1 = fmaxf(m1_, mx1);
        float cr0 = __expf(m0_ - mn0), cr1 = __expf(m1_ - mn1);
        m0_ = mn0; m1_ = mn1;
        float sum0 = 0.f, sum1 = 0.f;
#pragma unroll
        for (int nt = 0; nt < 2; nt++) {
            s[nt][0] = __expf(s[nt][0] - mn0); sum0 += s[nt][0];
            s[nt][1] = __expf(s[nt][1] - mn0); sum0 += s[nt][1];
            s[nt][2] = __expf(s[nt][2] - mn1); sum1 += s[nt][2];
            s[nt][3] = __expf(s[nt][3] - mn1); sum1 += s[nt][3];
        }
        sum0 += __shfl_xor_sync(0xffffffffu, sum0, 1);
        sum0 += __shfl_xor_sync(0xffffffffu, sum0, 2);
        sum1 += __shfl_xor_sync(0xffffffffu, sum1, 1);
        sum1 += __shfl_xor_sync(0xffffffffu, sum1, 2);
        l0_ = l0_ * cr0 + sum0;
        l1_ = l1_ * cr1 + sum1;
#pragma unroll
        for (int nt = 0; nt < 32; nt++) {
            o[nt][0] *= cr0; o[nt][1] *= cr0;
            o[nt][2] *= cr1; o[nt][3] *= cr1;
        }

        uint32_t pah[4];
        pah[0] = pack_h2(s[0][0], s[0][1]);
        pah[1] = pack_h2(s[0][2], s[0][3]);
        pah[2] = pack_h2(s[1][0], s[1][1]);
        pah[3] = pack_h2(s[1][2], s[1][3]);
#pragma unroll
        for (int n2 = 0; n2 < 16; n2++) {
            uint32_t r[4], vh0[2], vh1[2], vl0[2], vl1[2];
            uint32_t va = base + 16384 + (n2 >> 2) * 2048 +
                          SWZ128(rV * 128 + (n2 & 3) * 32 + cV);
            ldmx4t(r, va);
            vh0[0] = r[0]; vh0[1] = r[1]; vh1[0] = r[2]; vh1[1] = r[3];
            ldmx4t(r, va + 8192);
            vl0[0] = r[0]; vl0[1] = r[1]; vl1[0] = r[2]; vl1[1] = r[3];
            mma_f32(o[2*n2],   pah, vh0);
            mma_f32(o[2*n2+1], pah, vh1);
            mma_f32(o[2*n2],   pah, vl0);
            mma_f32(o[2*n2+1], pah, vl1);
        }
        __syncthreads();
    }

    float inv0 = 1.f / l0_, inv1 = 1.f / l1_;
    const long row0 = (long)(b * Sx + m0 + wid * 16 + gid) * Hx + h * 256;
    const long row1 = row0 + 8 * Hx;
#pragma unroll
    for (int nt = 0; nt < 32; nt++) {
        int d = nt * 8 + tig * 2;
        *(__half2*)(chi + row0 + d) = __halves2half2(
            __float2half(o[nt][0] * inv0), __float2half(o[nt][1] * inv0));
        *(__half2*)(chi + row1 + d) = __halves2half2(
            __float2half(o[nt][2] * inv1), __float2half(o[nt][3] * inv1));
    }
}

// ---------------------------------------------------------------------------
// conversions
// ---------------------------------------------------------------------------
struct WPack {
    const float* src[8];
    __half* dhi[8];
    int N[8];
    int tileOff[9];
};

__global__ void wsplit_all(WPack p)
{
    __shared__ float t[32][33];
    int bid = blockIdx.x;
    int w = 0;
    while (bid >= p.tileOff[w + 1]) w++;
    int tt = bid - p.tileOff[w];
    int ntx = p.N[w] >> 5;
    int n0 = (tt % ntx) * 32, k0 = (tt / ntx) * 32;
    const float* src = p.src[w];
    __half* hi = p.dhi[w];
    int N = p.N[w];
    int tx = threadIdx.x, ty = threadIdx.y;
    for (int j = ty; j < 32; j += 8)
        t[j][tx] = src[(long)(k0 + j) * N + n0 + tx];
    __syncthreads();
    for (int j = ty; j < 32; j += 8) {
        long o = (long)(n0 + j) * 1024 + k0 + tx;
        hi[o] = __float2half(t[tx][j]);
    }
}

__global__ void bcat_k(const float* __restrict__ bq, const float* __restrict__ bk,
                       const float* __restrict__ bv, float* __restrict__ dst)
{
    int i = blockIdx.x * 256 + threadIdx.x;
    if (i < 1024) dst[i] = bq[i];
    else if (i < 2048) dst[i] = bk[i - 1024];
    else if (i < 3072) dst[i] = bv[i - 2048];
}

// Fused: per row — xs_hi conversion + mod gate (amvec computed in-block)
__global__ void mod_k(const float* __restrict__ X, const float* __restrict__ cgW,
                      const float* __restrict__ cons, const float* __restrict__ amW,
                      const float* __restrict__ amb, const float* __restrict__ cgb,
                      __half* __restrict__ xs_hi, float* __restrict__ mod)
{
    __shared__ float xs[Hx];
    __shared__ float part[8][NHx];
    __shared__ float amv_s[NHx];
    int row = blockIdx.x;
    const float* x = X + (long)row * Hx;
    if (threadIdx.x < NHx) {
        int n = threadIdx.x;
        float s = amb[n] + cgb[n];
#pragma unroll
        for (int k = 0; k < 16; k++) s += cons[k] * amW[k * NHx + n];
        amv_s[n] = s;
    }
    for (int i = threadIdx.x; i < Hx; i += 128) {
        float v = x[i];
        xs[i] = v;
        xs_hi[(long)row * Hx + i] = __float2half(v);
    }
    __syncthreads();
    int n = threadIdx.x & 15;
    int g = threadIdx.x >> 4;
    float s = 0.f;
    for (int k = g; k < Hx; k += 8) s += xs[k] * cgW[k * NHx + n];
    part[g][n] = s;
    __syncthreads();
    if (threadIdx.x < NHx) {
        float t = amv_s[threadIdx.x];
#pragma unroll
        for (int gg = 0; gg < 8; gg++) t += part[gg][threadIdx.x];
        mod[(long)row * NHx + threadIdx.x] = 1.f / (1.f + __expf(-t));
    }
}

// ---------------------------------------------------------------------------
// Host side
// ---------------------------------------------------------------------------
template<typename T>
static T* symaddr(const void* sym) {
    void* p = nullptr;
    cudaGetSymbolAddress(&p, sym);
    return (T*)p;
}
typedef __half hf;

extern "C" void kernel_launch(void* const* d_in, const int* in_sizes, int n_in,
                              void* d_out, int out_size)
{
    (void)in_sizes; (void)n_in; (void)out_size;
    const float* X      = (const float*)d_in[0];
    const float* cons   = (const float*)d_in[1];
    const float* Wq     = (const float*)d_in[2];
    const float* bq     = (const float*)d_in[3];
    const float* Wk     = (const float*)d_in[4];
    const float* bk     = (const float*)d_in[5];
    const float* Wv     = (const float*)d_in[6];
    const float* bv     = (const float*)d_in[7];
    const float* cgW    = (const float*)d_in[8];
    const float* cgb    = (const float*)d_in[9];
    const float* amW    = (const float*)d_in[10];
    const float* amb    = (const float*)d_in[11];
    const float* caWin  = (const float*)d_in[12];
    const float* cabin  = (const float*)d_in[13];
    const float* caWout = (const float*)d_in[14];
    const float* cabout = (const float*)d_in[15];
    const float* mcWin  = (const float*)d_in[16];
    const float* mcbin  = (const float*)d_in[17];
    const float* mcWout = (const float*)d_in[18];
    const float* mcbout = (const float*)d_in[19];
    const float* Wo     = (const float*)d_in[20];
    const float* bo     = (const float*)d_in[21];
    float* out = (float*)d_out;

    hf *xs_hi = symaddr<hf>(g_xs_hi);
    hf *wqkvT_hi = symaddr<hf>(g_wqkvT_hi);
    hf *caWinT_hi = symaddr<hf>(g_caWinT_hi);
    hf *caWoutT_hi = symaddr<hf>(g_caWoutT_hi);
    hf *mcWinT_hi = symaddr<hf>(g_mcWinT_hi);
    hf *mcWoutT_hi = symaddr<hf>(g_mcWoutT_hi);
    hf *woT_hi = symaddr<hf>(g_woT_hi);
    hf *qk_hi = symaddr<hf>(g_qk_hi), *qk_lo = symaddr<hf>(g_qk_lo);
    hf *vT_hi = symaddr<hf>(g_vT_hi), *vT_lo = symaddr<hf>(g_vT_lo);
    hf *qkv_hi = symaddr<hf>(g_qkv_hi), *qkv_lo = symaddr<hf>(g_qkv_lo);
    hf *ctx2_hi = symaddr<hf>(g_ctx2_hi);
    hf *ctxb_hi = symaddr<hf>(g_ctxb_hi);
    hf *ctxm_hi = symaddr<hf>(g_ctxm_hi);
    float *ctx = symaddr<float>(g_ctx), *ctxb = symaddr<float>(g_ctxb);
    float *mod = symaddr<float>(g_mod);
    float *bqkv = symaddr<float>(g_bqkv);

    const int SMG  = 2 * 24576;          // 49152, 2 CTAs/SM
    const int SMFA = 16384 + 2 * 32768;  // 81920
    const int SMFB = 32768 + 2 * 32768;  // 98304, 2 CTAs/SM
    cudaFuncSetAttribute(gemm64,       cudaFuncAttributeMaxDynamicSharedMemorySize, SMG);
    cudaFuncSetAttribute(flash_main,   cudaFuncAttributeMaxDynamicSharedMemorySize, SMFA);
    cudaFuncSetAttribute(flash_branch, cudaFuncAttributeMaxDynamicSharedMemorySize, SMFB);

    const long SH = (long)Sx * Hx;
    dim3 tb(32, 8);
    dim3 gProj(Hx/64, MB/128, 1);        // 512 CTAs
    dim3 gQKV(3*Hx/64, MB/128, 1);       // 1536 CTAs

    WPack wp;
    wp.src[0] = Wq;     wp.dhi[0] = wqkvT_hi;               wp.N[0] = Hx;
    wp.src[1] = Wk;     wp.dhi[1] = wqkvT_hi + Hx * Hx;     wp.N[1] = Hx;
    wp.src[2] = Wv;     wp.dhi[2] = wqkvT_hi + 2 * Hx * Hx; wp.N[2] = Hx;
    wp.src[3] = caWin;  wp.dhi[3] = caWinT_hi;  wp.N[3] = 3 * Hx;
    wp.src[4] = caWout; wp.dhi[4] = caWoutT_hi; wp.N[4] = Hx;
    wp.src[5] = mcWin;  wp.dhi[5] = mcWinT_hi;  wp.N[5] = 3 * Hx;
    wp.src[6] = mcWout; wp.dhi[6] = mcWoutT_hi; wp.N[6] = Hx;
    wp.src[7] = Wo;     wp.dhi[7] = woT_hi;     wp.N[7] = Hx;
    wp.tileOff[0] = 0;
    for (int i = 0; i < 8; i++)
        wp.tileOff[i + 1] = wp.tileOff[i] + (wp.N[i] / 32) * (Hx / 32);

    // prep
    bcat_k<<<12, 256>>>(bq, bk, bv, bqkv);                                  // 0
    wsplit_all<<<wp.tileOff[8], tb>>>(wp);                                  // 1
    mod_k<<<MB, 128>>>(X, cgW, cons, amW, amb, cgb, xs_hi, mod);            // 2

    // 3: merged QKV projection: Q,K -> qk (ldc 2048), V -> transposed vT
    gemm64<<<gQKV, 256, SMG>>>(xs_hi, Hx, 0, 0,
        wqkvT_hi, Hx, 0, 0,
        nullptr, qk_hi, qk_lo, 2 * Hx, 0, 0,
        vT_hi, vT_lo, 2 * Hx, 3 * Hx, SH,
        Hx, 1, bqkv, 1.f, nullptr, 0, 0.f);

    // 4: fused main attention -> ctx (fp32)
    flash_main<<<dim3(Sx/128, Bx * NHx), 256, SMFA>>>(
        qk_hi, qk_lo, vT_hi, vT_lo, mod, ctx);

    // ---- causal + meta branches ----
    for (int br = 0; br < 2; br++) {
        const hf* winT_hi = br ? mcWinT_hi : caWinT_hi;
        const hf* woutT_hi = br ? mcWoutT_hi : caWoutT_hi;
        const float* bin  = br ? mcbin  : cabin;
        const float* bout = br ? mcbout : cabout;
        const hf* a_hi = br ? ctxb_hi : xs_hi;

        // in-proj: qkv = A @ Win + bin (split fp16 out — lo needed by attention)
        gemm64<<<gQKV, 256, SMG>>>(a_hi, Hx, 0, 0,
            winT_hi, Hx, 0, 0,
            nullptr, qkv_hi, qkv_lo, 3 * Hx, 0, 0,
            nullptr, nullptr, 0, 0, 0,
            Hx, 1, bin, 1.f, nullptr, 0, 0.f);
        // fused branch attention -> ctx2 (fp16 hi only)
        flash_branch<<<dim3(Sx/64, Bx * BR_HEADS), 128, SMFB>>>(
            qkv_hi, qkv_lo, ctx2_hi);
        // out-proj + blend
        if (br == 0) {
            gemm64<<<gProj, 256, SMG>>>(ctx2_hi, Hx, 0, 0,
                woutT_hi, Hx, 0, 0,
                ctxb, ctxb_hi, nullptr, Hx, 0, 0,
                nullptr, nullptr, 0, 0, 0,
                Hx, 1, bout, CAUSAL_W, ctx, Hx, 1.f - CAUSAL_W);
        } else {
            gemm64<<<gProj, 256, SMG>>>(ctx2_hi, Hx, 0, 0,
                woutT_hi, Hx, 0, 0,
                nullptr, ctxm_hi, nullptr, Hx, 0, 0,
                nullptr, nullptr, 0, 0, 0,
                Hx, 1, bout, META_W, ctxb, Hx, 1.f - META_W);
        }
    }

    // ---- final projection ----
    gemm64<<<gProj, 256, SMG>>>(ctxm_hi, Hx, 0, 0,
        woT_hi, Hx, 0, 0,
        out, nullptr, nullptr, Hx, 0, 0,
        nullptr, nullptr, 0, 0, 0,
        Hx, 1, bo, 1.f, nullptr, 0, 0.f);
}

// round 16
// speedup vs baseline: 1.4357x; 1.1793x over previous
#include <cuda_runtime.h>
#include <cuda_fp16.h>
#include <cstdint>
#include <math.h>

#define Bx 4
#define Sx 1024
#define Hx 1024
#define NHx 16
#define HDx 64
#define BR_HEADS 4
#define BR_HD 256
static const float CAUSAL_W = 0.7f;
static const float META_W  = 0.15f;

#define MB (Bx * Sx)   // 4096 rows

// ---------------------------------------------------------------------------
// Device scratch (pure fp16 operands)
// ---------------------------------------------------------------------------
__device__ __half g_xs_hi[MB * Hx];
__device__ __half g_wqkvT_hi[3 * Hx * Hx];
__device__ __half g_caWinT_hi[3 * Hx * Hx];
__device__ __half g_caWoutT_hi[Hx * Hx];
__device__ __half g_mcWinT_hi[3 * Hx * Hx];
__device__ __half g_mcWoutT_hi[Hx * Hx];
__device__ __half g_woT_hi[Hx * Hx];
__device__ float  g_bqkv[3 * Hx];

__device__ __half g_qk_hi[MB * 2 * Hx];        // [m][q(1024) k(1024)]
__device__ __half g_vT_hi[MB * Hx];            // [b][d][s]
__device__ __half g_qkv_hi[MB * 3 * Hx];

__device__ float g_ctx [MB * Hx];
__device__ float g_ctxb[MB * Hx];
__device__ __half g_ctx2_hi[MB * Hx];
__device__ __half g_ctxb_hi[MB * Hx];
__device__ __half g_ctxm_hi[MB * Hx];
__device__ float g_mod[MB * NHx];

// ---------------------------------------------------------------------------
// PTX helpers
// ---------------------------------------------------------------------------
__device__ __forceinline__ uint32_t smem_u32(const void* p) {
    uint32_t a;
    asm("{ .reg .u64 t; cvta.to.shared.u64 t, %1; cvt.u32.u64 %0, t; }" : "=r"(a) : "l"(p));
    return a;
}
#define SWZ128(o) ((o) ^ (((o) >> 3) & 0x70))

__device__ __forceinline__ void cp16(uint32_t s, const void* g) {
    asm volatile("cp.async.cg.shared.global [%0], [%1], 16;"
                 :: "r"(s), "l"(__cvta_generic_to_global(g)) : "memory");
}
#define CP_COMMIT() asm volatile("cp.async.commit_group;" ::: "memory")
template<int N> __device__ __forceinline__ void cp_wait() {
    asm volatile("cp.async.wait_group %0;" :: "n"(N) : "memory");
}
__device__ __forceinline__ void ldmx4(uint32_t* r, uint32_t a) {
    asm volatile("ldmatrix.sync.aligned.m8n8.x4.shared.b16 {%0,%1,%2,%3}, [%4];"
        : "=r"(r[0]), "=r"(r[1]), "=r"(r[2]), "=r"(r[3]) : "r"(a));
}
__device__ __forceinline__ void ldmx4t(uint32_t* r, uint32_t a) {
    asm volatile("ldmatrix.sync.aligned.m8n8.x4.trans.shared.b16 {%0,%1,%2,%3}, [%4];"
        : "=r"(r[0]), "=r"(r[1]), "=r"(r[2]), "=r"(r[3]) : "r"(a));
}
__device__ __forceinline__ void mma_f32(float* c, const uint32_t* a, const uint32_t* b) {
    asm volatile(
        "mma.sync.aligned.m16n8k16.row.col.f32.f16.f16.f32 "
        "{%0,%1,%2,%3}, {%4,%5,%6,%7}, {%8,%9}, {%0,%1,%2,%3};"
        : "+f"(c[0]), "+f"(c[1]), "+f"(c[2]), "+f"(c[3])
        : "r"(a[0]), "r"(a[1]), "r"(a[2]), "r"(a[3]), "r"(b[0]), "r"(b[1]));
}
__device__ __forceinline__ uint32_t pack_h2(float x, float y) {
    uint32_t r;
    asm("cvt.rn.f16x2.f32 %0, %1, %2;" : "=r"(r) : "f"(y), "f"(x));
    return r;
}

// ---------------------------------------------------------------------------
// 1-term fp16 GEMM: C = alpha*(Ah @ Bh^T + bias) + beta*blend.  (as R15,
// lo outputs now optional everywhere)
// ---------------------------------------------------------------------------
__global__ void __launch_bounds__(256, 2) gemm64(
    const __half* __restrict__ Ah, int lda, long sA1, long sA2,
    const __half* __restrict__ Bh, int ldb, long sB1, long sB2,
    float* Cf, __half* Chi,
    int ldc, long sC1, long sC2,
    __half* Thi, int tn0, int tn1, long TB,
    int K, int Z2,
    const float* __restrict__ bias, float alpha,
    const float* __restrict__ blend, int ldbl, float beta)
{
    constexpr int BSTG = 24576;
    extern __shared__ char dsm[];
    uint32_t sb = smem_u32(dsm);

    const int z = blockIdx.z, z1 = z / Z2, z2 = z % Z2;
    {
        Ah += z1 * sA1 + z2 * sA2;
        Bh += z1 * sB1 + z2 * sB2;
        long co = z1 * sC1 + z2 * sC2;
        if (Cf)  Cf  += co;
        if (Chi) Chi += co;
    }

    const int tid = threadIdx.x, lane = tid & 31, wid = tid >> 5;
    const int wm = wid >> 1, wn = wid & 1;
    const int m0 = blockIdx.y * 128, n0 = blockIdx.x * 64;

    float acc[2][4][4];
#pragma unroll
    for (int a = 0; a < 2; a++)
#pragma unroll
        for (int b = 0; b < 4; b++)
#pragma unroll
            for (int cc = 0; cc < 4; cc++) acc[a][b][cc] = 0.f;

    const int nk = K >> 6;

    auto fill = [&](int st, int c) {
        const int k0 = c << 6;
        const uint32_t base = sb + st * BSTG;
        for (int i = tid; i < 1024; i += 256) {       // A: 128 rows x 8 groups
            int row = i >> 3, gb = (i & 7) * 16;
            uint32_t sw = SWZ128(row * 128 + gb);
            cp16(base + sw, Ah + (long)(m0 + row) * lda + k0 + (gb >> 1));
        }
        for (int i = tid; i < 512; i += 256) {        // B: 64 rows x 8 groups
            int row = i >> 3, gb = (i & 7) * 16;
            uint32_t sw = SWZ128(row * 128 + gb);
            cp16(base + 16384 + sw, Bh + (long)(n0 + row) * ldb + k0 + (gb >> 1));
        }
    };

    const int rA = (lane & 7) + ((lane >> 3) & 1) * 8;
    const int cA = ((lane >> 4) & 1) * 16;
    const int rB = (lane & 7) + ((lane >> 4) & 1) * 8;
    const int cB = ((lane >> 3) & 1) * 16;

    fill(0, 0); CP_COMMIT();
    for (int c = 0; c < nk; c++) {
        if (c + 1 < nk) { fill((c + 1) & 1, c + 1); CP_COMMIT(); cp_wait<1>(); }
        else cp_wait<0>();
        __syncthreads();
        const uint32_t base = sb + (c & 1) * BSTG;
#pragma unroll
        for (int ks = 0; ks < 4; ks++) {
            uint32_t bh[4][2];
#pragma unroll
            for (int n2 = 0; n2 < 2; n2++) {
                uint32_t r[4];
                uint32_t bd = base + 16384 + SWZ128((wn * 32 + n2 * 16 + rB) * 128 + ks * 32 + cB);
                ldmx4(r, bd);
                bh[2*n2][0] = r[0]; bh[2*n2][1] = r[1];
                bh[2*n2+1][0] = r[2]; bh[2*n2+1][1] = r[3];
            }
            uint32_t ah[2][4];
#pragma unroll
            for (int mt = 0; mt < 2; mt++) {
                uint32_t ad = base + SWZ128((wm * 32 + mt * 16 + rA) * 128 + ks * 32 + cA);
                ldmx4(ah[mt], ad);
            }
#pragma unroll
            for (int mt = 0; mt < 2; mt++)
#pragma unroll
                for (int nt = 0; nt < 4; nt++)
                    mma_f32(acc[mt][nt], ah[mt], bh[nt]);
        }
        __syncthreads();
    }

    const int gid = lane >> 2, tig = lane & 3;
    auto store2 = [&](int m, int n, float v0, float v1) {
        if (bias) { v0 += bias[n]; v1 += bias[n + 1]; }
        v0 *= alpha; v1 *= alpha;
        if (blend) {
            const float* bp = blend + (long)m * ldbl + n;
            v0 += beta * bp[0]; v1 += beta * bp[1];
        }
        if (Cf) *(float2*)(Cf + (long)m * ldc + n) = make_float2(v0, v1);
        if (Chi && (!Thi || n < tn0)) {
            long o = (long)m * ldc + n;
            *(__half2*)(Chi + o) = __halves2half2(__float2half(v0), __float2half(v1));
        }
        if (Thi && n >= tn0 && n < tn1) {
            long o = (long)(m >> 10) * TB + (long)(n - tn0) * 1024 + (m & 1023);
            Thi[o] = __float2half(v0);
            Thi[o + 1024] = __float2half(v1);
        }
    };
#pragma unroll
    for (int mt = 0; mt < 2; mt++)
#pragma unroll
        for (int nt = 0; nt < 4; nt++) {
            int m = m0 + wm * 32 + mt * 16 + gid;
            int n = n0 + wn * 32 + nt * 8 + tig * 2;
            store2(m,     n, acc[mt][nt][0], acc[mt][nt][1]);
            store2(m + 8, n, acc[mt][nt][2], acc[mt][nt][3]);
        }
}

// ---------------------------------------------------------------------------
// Flash attention, main branch (HD=64, mod-gated, 1-term fp16).
// Q 16K + KV stages 2 x 16K (K 8K | V 8K) = 48K smem.
// ---------------------------------------------------------------------------
__global__ void __launch_bounds__(256) flash_main(
    const __half* __restrict__ qk_hi,
    const __half* __restrict__ vth_g,
    const float* __restrict__ mod, float* __restrict__ ctx)
{
    constexpr int OFF_KV = 16384, KVST = 16384;
    extern __shared__ char dsm[];
    uint32_t sb = smem_u32(dsm);

    const int z = blockIdx.y, b = z >> 4, h = z & 15;
    const int m0 = blockIdx.x * 128;
    const int tid = threadIdx.x, lane = tid & 31, wid = tid >> 5;
    const int gid = lane >> 2, tig = lane & 3;
    const long SHl = (long)Sx * Hx;

    const int rA = (lane & 7) + ((lane >> 3) & 1) * 8;
    const int cA = ((lane >> 4) & 1) * 16;
    const int rB = (lane & 7) + ((lane >> 4) & 1) * 8;
    const int cB = ((lane >> 3) & 1) * 16;

    for (int i = tid; i < 1024; i += 256) {
        int row = i >> 3, ch = i & 7;
        uint32_t sw = SWZ128(row * 128 + ch * 16);
        long go = (long)(b * Sx + m0 + row) * 2048 + h * 64 + ch * 8;
        cp16(sb + sw, qk_hi + go);
    }
    auto fillKV = [&](int st, int t) {
        const int kb = t * 64;
        const uint32_t base = sb + OFF_KV + st * KVST;
        for (int i = tid; i < 512; i += 256) {
            int row = i >> 3, ch = i & 7;
            uint32_t sw = SWZ128(row * 128 + ch * 16);
            long gk = (long)(b * Sx + kb + row) * 2048 + 1024 + h * 64 + ch * 8;
            long gv = (long)b * SHl + (long)(h * 64 + row) * Sx + kb + ch * 8;
            cp16(base + sw,        qk_hi + gk);
            cp16(base + 8192 + sw, vth_g + gv);
        }
    };
    fillKV(0, 0);
    CP_COMMIT();

    const int r0 = m0 + wid * 16 + gid;
    const float msc0 = 0.125f * mod[(long)(b * Sx + r0) * NHx + h];
    const float msc1 = 0.125f * mod[(long)(b * Sx + r0 + 8) * NHx + h];

    uint32_t qh[4][4];
    float o[8][4];
#pragma unroll
    for (int nt = 0; nt < 8; nt++)
#pragma unroll
        for (int c = 0; c < 4; c++) o[nt][c] = 0.f;
    float m0_ = -1e30f, m1_ = -1e30f, l0_ = 0.f, l1_ = 0.f;

    const int NTILE = Sx / 64;
    for (int t = 0; t < NTILE; t++) {
        if (t + 1 < NTILE) { fillKV((t + 1) & 1, t + 1); CP_COMMIT(); cp_wait<1>(); }
        else cp_wait<0>();
        __syncthreads();
        const uint32_t base = sb + OFF_KV + (t & 1) * KVST;

        if (t == 0) {
#pragma unroll
            for (int ks = 0; ks < 4; ks++) {
                uint32_t ad = sb + SWZ128((wid * 16 + rA) * 128 + ks * 32 + cA);
                ldmx4(qh[ks], ad);
            }
        }

        float s[8][4];
#pragma unroll
        for (int nt = 0; nt < 8; nt++)
#pragma unroll
            for (int c = 0; c < 4; c++) s[nt][c] = 0.f;
#pragma unroll
        for (int ks = 0; ks < 4; ks++) {
            uint32_t bh[8][2];
#pragma unroll
            for (int n2 = 0; n2 < 4; n2++) {
                uint32_t r[4];
                uint32_t bd = base + SWZ128((n2 * 16 + rB) * 128 + ks * 32 + cB);
                ldmx4(r, bd);
                bh[2*n2][0] = r[0]; bh[2*n2][1] = r[1];
                bh[2*n2+1][0] = r[2]; bh[2*n2+1][1] = r[3];
            }
#pragma unroll
            for (int nt = 0; nt < 8; nt++) mma_f32(s[nt], qh[ks], bh[nt]);
        }

        float mx0 = -1e30f, mx1 = -1e30f;
#pragma unroll
        for (int nt = 0; nt < 8; nt++) {
            s[nt][0] *= msc0; s[nt][1] *= msc0;
            s[nt][2] *= msc1; s[nt][3] *= msc1;
            mx0 = fmaxf(mx0, fmaxf(s[nt][0], s[nt][1]));
            mx1 = fmaxf(mx1, fmaxf(s[nt][2], s[nt][3]));
        }
        mx0 = fmaxf(mx0, __shfl_xor_sync(0xffffffffu, mx0, 1));
        mx0 = fmaxf(mx0, __shfl_xor_sync(0xffffffffu, mx0, 2));
        mx1 = fmaxf(mx1, __shfl_xor_sync(0xffffffffu, mx1, 1));
        mx1 = fmaxf(mx1, __shfl_xor_sync(0xffffffffu, mx1, 2));
        float mn0 = fmaxf(m0_, mx0), mn1 = fmaxf(m1_, mx1);
        float cr0 = __expf(m0_ - mn0), cr1 = __expf(m1_ - mn1);
        m0_ = mn0; m1_ = mn1;
        float sum0 = 0.f, sum1 = 0.f;
#pragma unroll
        for (int nt = 0; nt < 8; nt++) {
            s[nt][0] = __expf(s[nt][0] - mn0); sum0 += s[nt][0];
            s[nt][1] = __expf(s[nt][1] - mn0); sum0 += s[nt][1];
            s[nt][2] = __expf(s[nt][2] - mn1); sum1 += s[nt][2];
            s[nt][3] = __expf(s[nt][3] - mn1); sum1 += s[nt][3];
        }
        sum0 += __shfl_xor_sync(0xffffffffu, sum0, 1);
        sum0 += __shfl_xor_sync(0xffffffffu, sum0, 2);
        sum1 += __shfl_xor_sync(0xffffffffu, sum1, 1);
        sum1 += __shfl_xor_sync(0xffffffffu, sum1, 2);
        l0_ = l0_ * cr0 + sum0;
        l1_ = l1_ * cr1 + sum1;
#pragma unroll
        for (int nt = 0; nt < 8; nt++) {
            o[nt][0] *= cr0; o[nt][1] *= cr0;
            o[nt][2] *= cr1; o[nt][3] *= cr1;
        }

#pragma unroll
        for (int j = 0; j < 4; j++) {
            uint32_t pah[4];
            pah[0] = pack_h2(s[2*j][0],   s[2*j][1]);
            pah[1] = pack_h2(s[2*j][2],   s[2*j][3]);
            pah[2] = pack_h2(s[2*j+1][0], s[2*j+1][1]);
            pah[3] = pack_h2(s[2*j+1][2], s[2*j+1][3]);
            uint32_t vh[8][2];
#pragma unroll
            for (int n2 = 0; n2 < 4; n2++) {
                uint32_t r[4];
                uint32_t bd = base + 8192 + SWZ128((n2 * 16 + rB) * 128 + j * 32 + cB);
                ldmx4(r, bd);
                vh[2*n2][0] = r[0]; vh[2*n2][1] = r[1];
                vh[2*n2+1][0] = r[2]; vh[2*n2+1][1] = r[3];
            }
#pragma unroll
            for (int nt = 0; nt < 8; nt++) mma_f32(o[nt], pah, vh[nt]);
        }
        __syncthreads();
    }

    float inv0 = 1.f / l0_, inv1 = 1.f / l1_;
    const long row0 = (long)(b * Sx + r0) * Hx + h * 64;
    const long row1 = (long)(b * Sx + r0 + 8) * Hx + h * 64;
#pragma unroll
    for (int nt = 0; nt < 8; nt++) {
        int d = nt * 8 + tig * 2;
        *(float2*)(ctx + row0 + d) = make_float2(o[nt][0] * inv0, o[nt][1] * inv0);
        *(float2*)(ctx + row1 + d) = make_float2(o[nt][2] * inv1, o[nt][3] * inv1);
    }
}

// ---------------------------------------------------------------------------
// Flash attention, branch (HD=256, 4 heads, scale 1/16).  1-term fp16,
// double-buffered KV: Q 32K + 2 x 16K (K 8K | V 8K) = 64K smem, 2 CTAs/SM.
// ---------------------------------------------------------------------------
__global__ void __launch_bounds__(128, 2) flash_branch(
    const __half* __restrict__ qkv_hi,
    __half* __restrict__ chi)
{
    constexpr int OFF_KV = 32768, KVST = 16384;
    extern __shared__ char dsm[];
    uint32_t sb = smem_u32(dsm);

    const int b = blockIdx.y >> 2, h = blockIdx.y & 3;
    const int m0 = blockIdx.x * 64;
    const int tid = threadIdx.x, lane = tid & 31, wid = tid >> 5;
    const int gid = lane >> 2, tig = lane & 3;

    const int rA = (lane & 7) + ((lane >> 3) & 1) * 8;
    const int cA = ((lane >> 4) & 1) * 16;
    const int rB = (lane & 7) + ((lane >> 4) & 1) * 8;
    const int cB = ((lane >> 3) & 1) * 16;
    const int rV = lane & 15, cV = (lane >> 4) * 16;

    for (int i = tid; i < 2048; i += 128) {
        int row = i >> 5, ch = i & 31;
        uint32_t sw = (ch >> 3) * 8192 + SWZ128(row * 128 + (ch & 7) * 16);
        long g = (long)(b * Sx + m0 + row) * 3072 + h * 256 + ch * 8;
        cp16(sb + sw, qkv_hi + g);
    }
    auto fillKV = [&](int st, int t) {
        const int kb = t * 16;
        const uint32_t base = sb + OFF_KV + st * KVST;
        for (int i = tid; i < 512; i += 128) {
            int row = i >> 5, ch = i & 31;
            uint32_t sw = (ch >> 3) * 2048 + SWZ128(row * 128 + (ch & 7) * 16);
            long gk = (long)(b * Sx + kb + row) * 3072 + Hx + h * 256 + ch * 8;
            cp16(base + sw,        qkv_hi + gk);        // K
            cp16(base + 8192 + sw, qkv_hi + gk + Hx);   // V
        }
    };
    fillKV(0, 0);
    CP_COMMIT();

    float o[32][4];
#pragma unroll
    for (int nt = 0; nt < 32; nt++)
#pragma unroll
        for (int c = 0; c < 4; c++) o[nt][c] = 0.f;
    float m0_ = -1e30f, m1_ = -1e30f, l0_ = 0.f, l1_ = 0.f;

    for (int t = 0; t < 64; t++) {
        if (t + 1 < 64) { fillKV((t + 1) & 1, t + 1); CP_COMMIT(); cp_wait<1>(); }
        else cp_wait<0>();
        __syncthreads();
        const uint32_t base = sb + OFF_KV + (t & 1) * KVST;

        float s[2][4];
#pragma unroll
        for (int nt = 0; nt < 2; nt++)
#pragma unroll
            for (int c = 0; c < 4; c++) s[nt][c] = 0.f;
#pragma unroll
        for (int ks = 0; ks < 16; ks++) {
            uint32_t qh[4], r[4], kh[2][2];
            uint32_t qa = sb + (ks >> 2) * 8192 +
                          SWZ128((wid * 16 + rA) * 128 + (ks & 3) * 32 + cA);
            ldmx4(qh, qa);
            uint32_t ka = base + ((ks >> 2) & 3) * 2048 +
                          SWZ128(rB * 128 + (ks & 3) * 32 + cB);
            ldmx4(r, ka);
            kh[0][0] = r[0]; kh[0][1] = r[1]; kh[1][0] = r[2]; kh[1][1] = r[3];
#pragma unroll
            for (int nt = 0; nt < 2; nt++) mma_f32(s[nt], qh, kh[nt]);
        }

        float mx0 = -1e30f, mx1 = -1e30f;
#pragma unroll
        for (int nt = 0; nt < 2; nt++) {
            s[nt][0] *= 0.0625f; s[nt][1] *= 0.0625f;
            s[nt][2] *= 0.0625f; s[nt][3] *= 0.0625f;
            mx0 = fmaxf(mx0, fmaxf(s[nt][0], s[nt][1]));
            mx1 = fmaxf(mx1, fmaxf(s[nt][2], s[nt][3]));
        }
        mx0 = fmaxf(mx0, __shfl_xor_sync(0xffffffffu, mx0, 1));
        mx0 = fmaxf(mx0, __shfl_xor_sync(0xffffffffu, mx0, 2));
        mx1 = fmaxf(mx1, __shfl_xor_sync(0xffffffffu, mx1, 1));
        mx1 = fmaxf(mx1, __shfl_xor_sync(0xffffffffu, mx1, 2));
        float mn0 = fmaxf(m0_, mx0), mn1 = fmaxf(m1_, mx1);
        float cr0 = __expf(m0_ - mn0), cr1 = __expf(m1_ - mn1);
        m0_ = mn0; m1_ = mn1;
        float sum0 = 0.f, sum1 = 0.f;
#pragma unroll
        for (int nt = 0; nt < 2; nt++) {
            s[nt][0] = __expf(s[nt][0] - mn0); sum0 += s[nt][0];
            s[nt][1] = __expf(s[nt][1] - mn0); sum0 += s[nt][1];
            s[nt][2] = __expf(s[nt][2] - mn1); sum1 += s[nt][2];
            s[nt][3] = __expf(s[nt][3] - mn1); sum1 += s[nt][3];
        }
        sum0 += __shfl_xor_sync(0xffffffffu, sum0, 1);
        sum0 += __shfl_xor_sync(0xffffffffu, sum0, 2);
        sum1 += __shfl_xor_sync(0xffffffffu, sum1, 1);
        sum1 += __shfl_xor_sync(0xffffffffu, sum1, 2);
        l0_ = l0_ * cr0 + sum0;
        l1_ = l1_ * cr1 + sum1;
#pragma unroll
        for (int nt = 0; nt < 32; nt++) {
            o[nt][0] *= cr0; o[nt][1] *= cr0;
            o[nt][2] *= cr1; o[nt][3] *= cr1;
        }

        uint32_t pah[4];
        pah[0] = pack_h2(s[0][0], s[0][1]);
        pah[1] = pack_h2(s[0][2], s[0][3]);
        pah[2] = pack_h2(s[1][0], s[1][1]);
        pah[3] = pack_h2(s[1][2], s[1][3]);
#pragma unroll
        for (int n2 = 0; n2 < 16; n2++) {
            uint32_t r[4], vh0[2], vh1[2];
            uint32_t va = base + 8192 + (n2 >> 2) * 2048 +
                          SWZ128(rV * 128 + (n2 & 3) * 32 + cV);
            ldmx4t(r, va);
            vh0[0] = r[0]; vh0[1] = r[1]; vh1[0] = r[2]; vh1[1] = r[3];
            mma_f32(o[2*n2],   pah, vh0);
            mma_f32(o[2*n2+1], pah, vh1);
        }
        __syncthreads();
    }

    float inv0 = 1.f / l0_, inv1 = 1.f / l1_;
    const long row0 = (long)(b * Sx + m0 + wid * 16 + gid) * Hx + h * 256;
    const long row1 = row0 + 8 * Hx;
#pragma unroll
    for (int nt = 0; nt < 32; nt++) {
        int d = nt * 8 + tig * 2;
        *(__half2*)(chi + row0 + d) = __halves2half2(
            __float2half(o[nt][0] * inv0), __float2half(o[nt][1] * inv0));
        *(__half2*)(chi + row1 + d) = __halves2half2(
            __float2half(o[nt][2] * inv1), __float2half(o[nt][3] * inv1));
    }
}

// ---------------------------------------------------------------------------
// conversions
// ---------------------------------------------------------------------------
struct WPack {
    const float* src[8];
    __half* dhi[8];
    int N[8];
    int tileOff[9];
};

__global__ void wsplit_all(WPack p)
{
    __shared__ float t[32][33];
    int bid = blockIdx.x;
    int w = 0;
    while (bid >= p.tileOff[w + 1]) w++;
    int tt = bid - p.tileOff[w];
    int ntx = p.N[w] >> 5;
    int n0 = (tt % ntx) * 32, k0 = (tt / ntx) * 32;
    const float* src = p.src[w];
    __half* hi = p.dhi[w];
    int N = p.N[w];
    int tx = threadIdx.x, ty = threadIdx.y;
    for (int j = ty; j < 32; j += 8)
        t[j][tx] = src[(long)(k0 + j) * N + n0 + tx];
    __syncthreads();
    for (int j = ty; j < 32; j += 8) {
        long o = (long)(n0 + j) * 1024 + k0 + tx;
        hi[o] = __float2half(t[tx][j]);
    }
}

__global__ void bcat_k(const float* __restrict__ bq, const float* __restrict__ bk,
                       const float* __restrict__ bv, float* __restrict__ dst)
{
    int i = blockIdx.x * 256 + threadIdx.x;
    if (i < 1024) dst[i] = bq[i];
    else if (i < 2048) dst[i] = bk[i - 1024];
    else if (i < 3072) dst[i] = bv[i - 2048];
}

// Fused: per row — xs_hi conversion + mod gate (amvec computed in-block)
__global__ void mod_k(const float* __restrict__ X, const float* __restrict__ cgW,
                      const float* __restrict__ cons, const float* __restrict__ amW,
                      const float* __restrict__ amb, const float* __restrict__ cgb,
                      __half* __restrict__ xs_hi, float* __restrict__ mod)
{
    __shared__ float xs[Hx];
    __shared__ float part[8][NHx];
    __shared__ float amv_s[NHx];
    int row = blockIdx.x;
    const float* x = X + (long)row * Hx;
    if (threadIdx.x < NHx) {
        int n = threadIdx.x;
        float s = amb[n] + cgb[n];
#pragma unroll
        for (int k = 0; k < 16; k++) s += cons[k] * amW[k * NHx + n];
        amv_s[n] = s;
    }
    for (int i = threadIdx.x; i < Hx; i += 128) {
        float v = x[i];
        xs[i] = v;
        xs_hi[(long)row * Hx + i] = __float2half(v);
    }
    __syncthreads();
    int n = threadIdx.x & 15;
    int g = threadIdx.x >> 4;
    float s = 0.f;
    for (int k = g; k < Hx; k += 8) s += xs[k] * cgW[k * NHx + n];
    part[g][n] = s;
    __syncthreads();
    if (threadIdx.x < NHx) {
        float t = amv_s[threadIdx.x];
#pragma unroll
        for (int gg = 0; gg < 8; gg++) t += part[gg][threadIdx.x];
        mod[(long)row * NHx + threadIdx.x] = 1.f / (1.f + __expf(-t));
    }
}

// ---------------------------------------------------------------------------
// Host side
// ---------------------------------------------------------------------------
template<typename T>
static T* symaddr(const void* sym) {
    void* p = nullptr;
    cudaGetSymbolAddress(&p, sym);
    return (T*)p;
}
typedef __half hf;

extern "C" void kernel_launch(void* const* d_in, const int* in_sizes, int n_in,
                              void* d_out, int out_size)
{
    (void)in_sizes; (void)n_in; (void)out_size;
    const float* X      = (const float*)d_in[0];
    const float* cons   = (const float*)d_in[1];
    const float* Wq     = (const float*)d_in[2];
    const float* bq     = (const float*)d_in[3];
    const float* Wk     = (const float*)d_in[4];
    const float* bk     = (const float*)d_in[5];
    const float* Wv     = (const float*)d_in[6];
    const float* bv     = (const float*)d_in[7];
    const float* cgW    = (const float*)d_in[8];
    const float* cgb    = (const float*)d_in[9];
    const float* amW    = (const float*)d_in[10];
    const float* amb    = (const float*)d_in[11];
    const float* caWin  = (const float*)d_in[12];
    const float* cabin  = (const float*)d_in[13];
    const float* caWout = (const float*)d_in[14];
    const float* cabout = (const float*)d_in[15];
    const float* mcWin  = (const float*)d_in[16];
    const float* mcbin  = (const float*)d_in[17];
    const float* mcWout = (const float*)d_in[18];
    const float* mcbout = (const float*)d_in[19];
    const float* Wo     = (const float*)d_in[20];
    const float* bo     = (const float*)d_in[21];
    float* out = (float*)d_out;

    hf *xs_hi = symaddr<hf>(g_xs_hi);
    hf *wqkvT_hi = symaddr<hf>(g_wqkvT_hi);
    hf *caWinT_hi = symaddr<hf>(g_caWinT_hi);
    hf *caWoutT_hi = symaddr<hf>(g_caWoutT_hi);
    hf *mcWinT_hi = symaddr<hf>(g_mcWinT_hi);
    hf *mcWoutT_hi = symaddr<hf>(g_mcWoutT_hi);
    hf *woT_hi = symaddr<hf>(g_woT_hi);
    hf *qk_hi = symaddr<hf>(g_qk_hi);
    hf *vT_hi = symaddr<hf>(g_vT_hi);
    hf *qkv_hi = symaddr<hf>(g_qkv_hi);
    hf *ctx2_hi = symaddr<hf>(g_ctx2_hi);
    hf *ctxb_hi = symaddr<hf>(g_ctxb_hi);
    hf *ctxm_hi = symaddr<hf>(g_ctxm_hi);
    float *ctx = symaddr<float>(g_ctx), *ctxb = symaddr<float>(g_ctxb);
    float *mod = symaddr<float>(g_mod);
    float *bqkv = symaddr<float>(g_bqkv);

    const int SMG  = 2 * 24576;          // 49152, 2 CTAs/SM
    const int SMFA = 16384 + 2 * 16384;  // 49152
    const int SMFB = 32768 + 2 * 16384;  // 65536, 2 CTAs/SM
    cudaFuncSetAttribute(gemm64,       cudaFuncAttributeMaxDynamicSharedMemorySize, SMG);
    cudaFuncSetAttribute(flash_main,   cudaFuncAttributeMaxDynamicSharedMemorySize, SMFA);
    cudaFuncSetAttribute(flash_branch, cudaFuncAttributeMaxDynamicSharedMemorySize, SMFB);

    const long SH = (long)Sx * Hx;
    dim3 tb(32, 8);
    dim3 gProj(Hx/64, MB/128, 1);        // 512 CTAs
    dim3 gQKV(3*Hx/64, MB/128, 1);       // 1536 CTAs

    WPack wp;
    wp.src[0] = Wq;     wp.dhi[0] = wqkvT_hi;               wp.N[0] = Hx;
    wp.src[1] = Wk;     wp.dhi[1] = wqkvT_hi + Hx * Hx;     wp.N[1] = Hx;
    wp.src[2] = Wv;     wp.dhi[2] = wqkvT_hi + 2 * Hx * Hx; wp.N[2] = Hx;
    wp.src[3] = caWin;  wp.dhi[3] = caWinT_hi;  wp.N[3] = 3 * Hx;
    wp.src[4] = caWout; wp.dhi[4] = caWoutT_hi; wp.N[4] = Hx;
    wp.src[5] = mcWin;  wp.dhi[5] = mcWinT_hi;  wp.N[5] = 3 * Hx;
    wp.src[6] = mcWout; wp.dhi[6] = mcWoutT_hi; wp.N[6] = Hx;
    wp.src[7] = Wo;     wp.dhi[7] = woT_hi;     wp.N[7] = Hx;
    wp.tileOff[0] = 0;
    for (int i = 0; i < 8; i++)
        wp.tileOff[i + 1] = wp.tileOff[i] + (wp.N[i] / 32) * (Hx / 32);

    // prep
    bcat_k<<<12, 256>>>(bq, bk, bv, bqkv);                                  // 0
    wsplit_all<<<wp.tileOff[8], tb>>>(wp);                                  // 1
    mod_k<<<MB, 128>>>(X, cgW, cons, amW, amb, cgb, xs_hi, mod);            // 2

    // 3: merged QKV projection: Q,K -> qk (ldc 2048), V -> transposed vT
    gemm64<<<gQKV, 256, SMG>>>(xs_hi, Hx, 0, 0,
        wqkvT_hi, Hx, 0, 0,
        nullptr, qk_hi, 2 * Hx, 0, 0,
        vT_hi, 2 * Hx, 3 * Hx, SH,
        Hx, 1, bqkv, 1.f, nullptr, 0, 0.f);

    // 4: fused main attention -> ctx (fp32)
    flash_main<<<dim3(Sx/128, Bx * NHx), 256, SMFA>>>(
        qk_hi, vT_hi, mod, ctx);

    // ---- causal + meta branches ----
    for (int br = 0; br < 2; br++) {
        const hf* winT_hi = br ? mcWinT_hi : caWinT_hi;
        const hf* woutT_hi = br ? mcWoutT_hi : caWoutT_hi;
        const float* bin  = br ? mcbin  : cabin;
        const float* bout = br ? mcbout : cabout;
        const hf* a_hi = br ? ctxb_hi : xs_hi;

        // in-proj: qkv = A @ Win + bin (fp16 out)
        gemm64<<<gQKV, 256, SMG>>>(a_hi, Hx, 0, 0,
            winT_hi, Hx, 0, 0,
            nullptr, qkv_hi, 3 * Hx, 0, 0,
            nullptr, 0, 0, 0,
            Hx, 1, bin, 1.f, nullptr, 0, 0.f);
        // fused branch attention -> ctx2 (fp16)
        flash_branch<<<dim3(Sx/64, Bx * BR_HEADS), 128, SMFB>>>(
            qkv_hi, ctx2_hi);
        // out-proj + blend
        if (br == 0) {
            gemm64<<<gProj, 256, SMG>>>(ctx2_hi, Hx, 0, 0,
                woutT_hi, Hx, 0, 0,
                ctxb, ctxb_hi, Hx, 0, 0,
                nullptr, 0, 0, 0,
                Hx, 1, bout, CAUSAL_W, ctx, Hx, 1.f - CAUSAL_W);
        } else {
            gemm64<<<gProj, 256, SMG>>>(ctx2_hi, Hx, 0, 0,
                woutT_hi, Hx, 0, 0,
                nullptr, ctxm_hi, Hx, 0, 0,
                nullptr, 0, 0, 0,
                Hx, 1, bout, META_W, ctxb, Hx, 1.f - META_W);
        }
    }

    // ---- final projection ----
    gemm64<<<gProj, 256, SMG>>>(ctxm_hi, Hx, 0, 0,
        woT_hi, Hx, 0, 0,
        out, nullptr, Hx, 0, 0,
        nullptr, 0, 0, 0,
        Hx, 1, bo, 1.f, nullptr, 0, 0.f);
}

// round 17
// speedup vs baseline: 1.4848x; 1.0342x over previous
#include <cuda_runtime.h>
#include <cuda_fp16.h>
#include <cstdint>
#include <math.h>

#define Bx 4
#define Sx 1024
#define Hx 1024
#define NHx 16
#define HDx 64
#define BR_HEADS 4
#define BR_HD 256
static const float CAUSAL_W = 0.7f;
static const float META_W  = 0.15f;

#define MB (Bx * Sx)   // 4096 rows

// ---------------------------------------------------------------------------
// Device scratch (pure fp16 operands)
// ---------------------------------------------------------------------------
__device__ __half g_xs_hi[MB * Hx];
__device__ __half g_wqkvT_hi[3 * Hx * Hx];
__device__ __half g_caWinT_hi[3 * Hx * Hx];
__device__ __half g_caWoutT_hi[Hx * Hx];
__device__ __half g_mcWinT_hi[3 * Hx * Hx];
__device__ __half g_mcWoutT_hi[Hx * Hx];
__device__ __half g_woT_hi[Hx * Hx];
__device__ float  g_bqkv[3 * Hx];

__device__ __half g_qk_hi[MB * 2 * Hx];        // [m][q(1024) k(1024)]
__device__ __half g_vT_hi[MB * Hx];            // [b][d][s]
__device__ __half g_qkv_hi[MB * 3 * Hx];

__device__ float g_ctx [MB * Hx];
__device__ float g_ctxb[MB * Hx];
__device__ __half g_ctx2_hi[MB * Hx];
__device__ __half g_ctxb_hi[MB * Hx];
__device__ __half g_ctxm_hi[MB * Hx];
__device__ float g_mod[MB * NHx];

// ---------------------------------------------------------------------------
// PTX helpers
// ---------------------------------------------------------------------------
__device__ __forceinline__ uint32_t smem_u32(const void* p) {
    uint32_t a;
    asm("{ .reg .u64 t; cvta.to.shared.u64 t, %1; cvt.u32.u64 %0, t; }" : "=r"(a) : "l"(p));
    return a;
}
#define SWZ128(o) ((o) ^ (((o) >> 3) & 0x70))

__device__ __forceinline__ void cp16(uint32_t s, const void* g) {
    asm volatile("cp.async.cg.shared.global [%0], [%1], 16;"
                 :: "r"(s), "l"(__cvta_generic_to_global(g)) : "memory");
}
#define CP_COMMIT() asm volatile("cp.async.commit_group;" ::: "memory")
template<int N> __device__ __forceinline__ void cp_wait() {
    asm volatile("cp.async.wait_group %0;" :: "n"(N) : "memory");
}
__device__ __forceinline__ void ldmx4(uint32_t* r, uint32_t a) {
    asm volatile("ldmatrix.sync.aligned.m8n8.x4.shared.b16 {%0,%1,%2,%3}, [%4];"
        : "=r"(r[0]), "=r"(r[1]), "=r"(r[2]), "=r"(r[3]) : "r"(a));
}
__device__ __forceinline__ void ldmx4t(uint32_t* r, uint32_t a) {
    asm volatile("ldmatrix.sync.aligned.m8n8.x4.trans.shared.b16 {%0,%1,%2,%3}, [%4];"
        : "=r"(r[0]), "=r"(r[1]), "=r"(r[2]), "=r"(r[3]) : "r"(a));
}
__device__ __forceinline__ void mma_f32(float* c, const uint32_t* a, const uint32_t* b) {
    asm volatile(
        "mma.sync.aligned.m16n8k16.row.col.f32.f16.f16.f32 "
        "{%0,%1,%2,%3}, {%4,%5,%6,%7}, {%8,%9}, {%0,%1,%2,%3};"
        : "+f"(c[0]), "+f"(c[1]), "+f"(c[2]), "+f"(c[3])
        : "r"(a[0]), "r"(a[1]), "r"(a[2]), "r"(a[3]), "r"(b[0]), "r"(b[1]));
}
__device__ __forceinline__ uint32_t pack_h2(float x, float y) {
    uint32_t r;
    asm("cvt.rn.f16x2.f32 %0, %1, %2;" : "=r"(r) : "f"(y), "f"(x));
    return r;
}

// ---------------------------------------------------------------------------
// 1-term fp16 GEMM: C = alpha*(Ah @ Bh^T + bias) + beta*blend.
// BM=128 x BN=128, BK=64, 8 warps (2m x 4n), warp tile 64x32 (acc 64 regs).
// MMA:LDSM = 16:6 per k-step.  2-stage cp.async, stage = A16K | B16K = 32K
// -> 64K total, 2 CTAs/SM.
// ---------------------------------------------------------------------------
__global__ void __launch_bounds__(256, 2) gemm128(
    const __half* __restrict__ Ah, int lda, long sA1, long sA2,
    const __half* __restrict__ Bh, int ldb, long sB1, long sB2,
    float* Cf, __half* Chi,
    int ldc, long sC1, long sC2,
    __half* Thi, int tn0, int tn1, long TB,
    int K, int Z2,
    const float* __restrict__ bias, float alpha,
    const float* __restrict__ blend, int ldbl, float beta)
{
    constexpr int BSTG = 32768;
    extern __shared__ char dsm[];
    uint32_t sb = smem_u32(dsm);

    const int z = blockIdx.z, z1 = z / Z2, z2 = z % Z2;
    {
        Ah += z1 * sA1 + z2 * sA2;
        Bh += z1 * sB1 + z2 * sB2;
        long co = z1 * sC1 + z2 * sC2;
        if (Cf)  Cf  += co;
        if (Chi) Chi += co;
    }

    const int tid = threadIdx.x, lane = tid & 31, wid = tid >> 5;
    const int wm = wid >> 2, wn = wid & 3;           // 2m x 4n warp grid
    const int m0 = blockIdx.y * 128, n0 = blockIdx.x * 128;

    float acc[4][4][4];                              // mt x nt x frag (64 regs)
#pragma unroll
    for (int a = 0; a < 4; a++)
#pragma unroll
        for (int b = 0; b < 4; b++)
#pragma unroll
            for (int cc = 0; cc < 4; cc++) acc[a][b][cc] = 0.f;

    const int nk = K >> 6;

    auto fill = [&](int st, int c) {
        const int k0 = c << 6;
        const uint32_t base = sb + st * BSTG;
        for (int i = tid; i < 1024; i += 256) {       // A: 128 rows x 8 groups
            int row = i >> 3, gb = (i & 7) * 16;
            uint32_t sw = SWZ128(row * 128 + gb);
            cp16(base + sw, Ah + (long)(m0 + row) * lda + k0 + (gb >> 1));
        }
        for (int i = tid; i < 1024; i += 256) {       // B: 128 rows x 8 groups
            int row = i >> 3, gb = (i & 7) * 16;
            uint32_t sw = SWZ128(row * 128 + gb);
            cp16(base + 16384 + sw, Bh + (long)(n0 + row) * ldb + k0 + (gb >> 1));
        }
    };

    const int rA = (lane & 7) + ((lane >> 3) & 1) * 8;
    const int cA = ((lane >> 4) & 1) * 16;
    const int rB = (lane & 7) + ((lane >> 4) & 1) * 8;
    const int cB = ((lane >> 3) & 1) * 16;

    fill(0, 0); CP_COMMIT();
    for (int c = 0; c < nk; c++) {
        if (c + 1 < nk) { fill((c + 1) & 1, c + 1); CP_COMMIT(); cp_wait<1>(); }
        else cp_wait<0>();
        __syncthreads();
        const uint32_t base = sb + (c & 1) * BSTG;
#pragma unroll
        for (int ks = 0; ks < 4; ks++) {
            uint32_t bh[4][2];
#pragma unroll
            for (int n2 = 0; n2 < 2; n2++) {
                uint32_t r[4];
                uint32_t bd = base + 16384 + SWZ128((wn * 32 + n2 * 16 + rB) * 128 + ks * 32 + cB);
                ldmx4(r, bd);
                bh[2*n2][0] = r[0]; bh[2*n2][1] = r[1];
                bh[2*n2+1][0] = r[2]; bh[2*n2+1][1] = r[3];
            }
            uint32_t ah[4][4];
#pragma unroll
            for (int mt = 0; mt < 4; mt++) {
                uint32_t ad = base + SWZ128((wm * 64 + mt * 16 + rA) * 128 + ks * 32 + cA);
                ldmx4(ah[mt], ad);
            }
#pragma unroll
            for (int mt = 0; mt < 4; mt++)
#pragma unroll
                for (int nt = 0; nt < 4; nt++)
                    mma_f32(acc[mt][nt], ah[mt], bh[nt]);
        }
        __syncthreads();
    }

    const int gid = lane >> 2, tig = lane & 3;
    auto store2 = [&](int m, int n, float v0, float v1) {
        if (bias) { v0 += bias[n]; v1 += bias[n + 1]; }
        v0 *= alpha; v1 *= alpha;
        if (blend) {
            const float* bp = blend + (long)m * ldbl + n;
            v0 += beta * bp[0]; v1 += beta * bp[1];
        }
        if (Cf) *(float2*)(Cf + (long)m * ldc + n) = make_float2(v0, v1);
        if (Chi && (!Thi || n < tn0)) {
            long o = (long)m * ldc + n;
            *(__half2*)(Chi + o) = __halves2half2(__float2half(v0), __float2half(v1));
        }
        if (Thi && n >= tn0 && n < tn1) {
            long o = (long)(m >> 10) * TB + (long)(n - tn0) * 1024 + (m & 1023);
            Thi[o] = __float2half(v0);
            Thi[o + 1024] = __float2half(v1);
        }
    };
#pragma unroll
    for (int mt = 0; mt < 4; mt++)
#pragma unroll
        for (int nt = 0; nt < 4; nt++) {
            int m = m0 + wm * 64 + mt * 16 + gid;
            int n = n0 + wn * 32 + nt * 8 + tig * 2;
            store2(m,     n, acc[mt][nt][0], acc[mt][nt][1]);
            store2(m + 8, n, acc[mt][nt][2], acc[mt][nt][3]);
        }
}

// ---------------------------------------------------------------------------
// Flash attention, main branch (HD=64, mod-gated, 1-term fp16).  (as R16)
// ---------------------------------------------------------------------------
__global__ void __launch_bounds__(256) flash_main(
    const __half* __restrict__ qk_hi,
    const __half* __restrict__ vth_g,
    const float* __restrict__ mod, float* __restrict__ ctx)
{
    constexpr int OFF_KV = 16384, KVST = 16384;
    extern __shared__ char dsm[];
    uint32_t sb = smem_u32(dsm);

    const int z = blockIdx.y, b = z >> 4, h = z & 15;
    const int m0 = blockIdx.x * 128;
    const int tid = threadIdx.x, lane = tid & 31, wid = tid >> 5;
    const int gid = lane >> 2, tig = lane & 3;
    const long SHl = (long)Sx * Hx;

    const int rA = (lane & 7) + ((lane >> 3) & 1) * 8;
    const int cA = ((lane >> 4) & 1) * 16;
    const int rB = (lane & 7) + ((lane >> 4) & 1) * 8;
    const int cB = ((lane >> 3) & 1) * 16;

    for (int i = tid; i < 1024; i += 256) {
        int row = i >> 3, ch = i & 7;
        uint32_t sw = SWZ128(row * 128 + ch * 16);
        long go = (long)(b * Sx + m0 + row) * 2048 + h * 64 + ch * 8;
        cp16(sb + sw, qk_hi + go);
    }
    auto fillKV = [&](int st, int t) {
        const int kb = t * 64;
        const uint32_t base = sb + OFF_KV + st * KVST;
        for (int i = tid; i < 512; i += 256) {
            int row = i >> 3, ch = i & 7;
            uint32_t sw = SWZ128(row * 128 + ch * 16);
            long gk = (long)(b * Sx + kb + row) * 2048 + 1024 + h * 64 + ch * 8;
            long gv = (long)b * SHl + (long)(h * 64 + row) * Sx + kb + ch * 8;
            cp16(base + sw,        qk_hi + gk);
            cp16(base + 8192 + sw, vth_g + gv);
        }
    };
    fillKV(0, 0);
    CP_COMMIT();

    const int r0 = m0 + wid * 16 + gid;
    const float msc0 = 0.125f * mod[(long)(b * Sx + r0) * NHx + h];
    const float msc1 = 0.125f * mod[(long)(b * Sx + r0 + 8) * NHx + h];

    uint32_t qh[4][4];
    float o[8][4];
#pragma unroll
    for (int nt = 0; nt < 8; nt++)
#pragma unroll
        for (int c = 0; c < 4; c++) o[nt][c] = 0.f;
    float m0_ = -1e30f, m1_ = -1e30f, l0_ = 0.f, l1_ = 0.f;

    const int NTILE = Sx / 64;
    for (int t = 0; t < NTILE; t++) {
        if (t + 1 < NTILE) { fillKV((t + 1) & 1, t + 1); CP_COMMIT(); cp_wait<1>(); }
        else cp_wait<0>();
        __syncthreads();
        const uint32_t base = sb + OFF_KV + (t & 1) * KVST;

        if (t == 0) {
#pragma unroll
            for (int ks = 0; ks < 4; ks++) {
                uint32_t ad = sb + SWZ128((wid * 16 + rA) * 128 + ks * 32 + cA);
                ldmx4(qh[ks], ad);
            }
        }

        float s[8][4];
#pragma unroll
        for (int nt = 0; nt < 8; nt++)
#pragma unroll
            for (int c = 0; c < 4; c++) s[nt][c] = 0.f;
#pragma unroll
        for (int ks = 0; ks < 4; ks++) {
            uint32_t bh[8][2];
#pragma unroll
            for (int n2 = 0; n2 < 4; n2++) {
                uint32_t r[4];
                uint32_t bd = base + SWZ128((n2 * 16 + rB) * 128 + ks * 32 + cB);
                ldmx4(r, bd);
                bh[2*n2][0] = r[0]; bh[2*n2][1] = r[1];
                bh[2*n2+1][0] = r[2]; bh[2*n2+1][1] = r[3];
            }
#pragma unroll
            for (int nt = 0; nt < 8; nt++) mma_f32(s[nt], qh[ks], bh[nt]);
        }

        float mx0 = -1e30f, mx1 = -1e30f;
#pragma unroll
        for (int nt = 0; nt < 8; nt++) {
            s[nt][0] *= msc0; s[nt][1] *= msc0;
            s[nt][2] *= msc1; s[nt][3] *= msc1;
            mx0 = fmaxf(mx0, fmaxf(s[nt][0], s[nt][1]));
            mx1 = fmaxf(mx1, fmaxf(s[nt][2], s[nt][3]));
        }
        mx0 = fmaxf(mx0, __shfl_xor_sync(0xffffffffu, mx0, 1));
        mx0 = fmaxf(mx0, __shfl_xor_sync(0xffffffffu, mx0, 2));
        mx1 = fmaxf(mx1, __shfl_xor_sync(0xffffffffu, mx1, 1));
        mx1 = fmaxf(mx1, __shfl_xor_sync(0xffffffffu, mx1, 2));
        float mn0 = fmaxf(m0_, mx0), mn1 = fmaxf(m1_, mx1);
        float cr0 = __expf(m0_ - mn0), cr1 = __expf(m1_ - mn1);
        m0_ = mn0; m1_ = mn1;
        float sum0 = 0.f, sum1 = 0.f;
#pragma unroll
        for (int nt = 0; nt < 8; nt++) {
            s[nt][0] = __expf(s[nt][0] - mn0); sum0 += s[nt][0];
            s[nt][1] = __expf(s[nt][1] - mn0); sum0 += s[nt][1];
            s[nt][2] = __expf(s[nt][2] - mn1); sum1 += s[nt][2];
            s[nt][3] = __expf(s[nt][3] - mn1); sum1 += s[nt][3];
        }
        sum0 += __shfl_xor_sync(0xffffffffu, sum0, 1);
        sum0 += __shfl_xor_sync(0xffffffffu, sum0, 2);
        sum1 += __shfl_xor_sync(0xffffffffu, sum1, 1);
        sum1 += __shfl_xor_sync(0xffffffffu, sum1, 2);
        l0_ = l0_ * cr0 + sum0;
        l1_ = l1_ * cr1 + sum1;
#pragma unroll
        for (int nt = 0; nt < 8; nt++) {
            o[nt][0] *= cr0; o[nt][1] *= cr0;
            o[nt][2] *= cr1; o[nt][3] *= cr1;
        }

#pragma unroll
        for (int j = 0; j < 4; j++) {
            uint32_t pah[4];
            pah[0] = pack_h2(s[2*j][0],   s[2*j][1]);
            pah[1] = pack_h2(s[2*j][2],   s[2*j][3]);
            pah[2] = pack_h2(s[2*j+1][0], s[2*j+1][1]);
            pah[3] = pack_h2(s[2*j+1][2], s[2*j+1][3]);
            uint32_t vh[8][2];
#pragma unroll
            for (int n2 = 0; n2 < 4; n2++) {
                uint32_t r[4];
                uint32_t bd = base + 8192 + SWZ128((n2 * 16 + rB) * 128 + j * 32 + cB);
                ldmx4(r, bd);
                vh[2*n2][0] = r[0]; vh[2*n2][1] = r[1];
                vh[2*n2+1][0] = r[2]; vh[2*n2+1][1] = r[3];
            }
#pragma unroll
            for (int nt = 0; nt < 8; nt++) mma_f32(o[nt], pah, vh[nt]);
        }
        __syncthreads();
    }

    float inv0 = 1.f / l0_, inv1 = 1.f / l1_;
    const long row0 = (long)(b * Sx + r0) * Hx + h * 64;
    const long row1 = (long)(b * Sx + r0 + 8) * Hx + h * 64;
#pragma unroll
    for (int nt = 0; nt < 8; nt++) {
        int d = nt * 8 + tig * 2;
        *(float2*)(ctx + row0 + d) = make_float2(o[nt][0] * inv0, o[nt][1] * inv0);
        *(float2*)(ctx + row1 + d) = make_float2(o[nt][2] * inv1, o[nt][3] * inv1);
    }
}

// ---------------------------------------------------------------------------
// Flash attention, branch (HD=256, 4 heads, scale 1/16).  1-term fp16,
// double-buffered KV.  (as R16)
// ---------------------------------------------------------------------------
__global__ void __launch_bounds__(128, 2) flash_branch(
    const __half* __restrict__ qkv_hi,
    __half* __restrict__ chi)
{
    constexpr int OFF_KV = 32768, KVST = 16384;
    extern __shared__ char dsm[];
    uint32_t sb = smem_u32(dsm);

    const int b = blockIdx.y >> 2, h = blockIdx.y & 3;
    const int m0 = blockIdx.x * 64;
    const int tid = threadIdx.x, lane = tid & 31, wid = tid >> 5;
    const int gid = lane >> 2, tig = lane & 3;

    const int rA = (lane & 7) + ((lane >> 3) & 1) * 8;
    const int cA = ((lane >> 4) & 1) * 16;
    const int rB = (lane & 7) + ((lane >> 4) & 1) * 8;
    const int cB = ((lane >> 3) & 1) * 16;
    const int rV = lane & 15, cV = (lane >> 4) * 16;

    for (int i = tid; i < 2048; i += 128) {
        int row = i >> 5, ch = i & 31;
        uint32_t sw = (ch >> 3) * 8192 + SWZ128(row * 128 + (ch & 7) * 16);
        long g = (long)(b * Sx + m0 + row) * 3072 + h * 256 + ch * 8;
        cp16(sb + sw, qkv_hi + g);
    }
    auto fillKV = [&](int st, int t) {
        const int kb = t * 16;
        const uint32_t base = sb + OFF_KV + st * KVST;
        for (int i = tid; i < 512; i += 128) {
            int row = i >> 5, ch = i & 31;
            uint32_t sw = (ch >> 3) * 2048 + SWZ128(row * 128 + (ch & 7) * 16);
            long gk = (long)(b * Sx + kb + row) * 3072 + Hx + h * 256 + ch * 8;
            cp16(base + sw,        qkv_hi + gk);        // K
            cp16(base + 8192 + sw, qkv_hi + gk + Hx);   // V
        }
    };
    fillKV(0, 0);
    CP_COMMIT();

    float o[32][4];
#pragma unroll
    for (int nt = 0; nt < 32; nt++)
#pragma unroll
        for (int c = 0; c < 4; c++) o[nt][c] = 0.f;
    float m0_ = -1e30f, m1_ = -1e30f, l0_ = 0.f, l1_ = 0.f;

    for (int t = 0; t < 64; t++) {
        if (t + 1 < 64) { fillKV((t + 1) & 1, t + 1); CP_COMMIT(); cp_wait<1>(); }
        else cp_wait<0>();
        __syncthreads();
        const uint32_t base = sb + OFF_KV + (t & 1) * KVST;

        float s[2][4];
#pragma unroll
        for (int nt = 0; nt < 2; nt++)
#pragma unroll
            for (int c = 0; c < 4; c++) s[nt][c] = 0.f;
#pragma unroll
        for (int ks = 0; ks < 16; ks++) {
            uint32_t qh[4], r[4], kh[2][2];
            uint32_t qa = sb + (ks >> 2) * 8192 +
                          SWZ128((wid * 16 + rA) * 128 + (ks & 3) * 32 + cA);
            ldmx4(qh, qa);
            uint32_t ka = base + ((ks >> 2) & 3) * 2048 +
                          SWZ128(rB * 128 + (ks & 3) * 32 + cB);
            ldmx4(r, ka);
            kh[0][0] = r[0]; kh[0][1] = r[1]; kh[1][0] = r[2]; kh[1][1] = r[3];
#pragma unroll
            for (int nt = 0; nt < 2; nt++) mma_f32(s[nt], qh, kh[nt]);
        }

        float mx0 = -1e30f, mx1 = -1e30f;
#pragma unroll
        for (int nt = 0; nt < 2; nt++) {
            s[nt][0] *= 0.0625f; s[nt][1] *= 0.0625f;
            s[nt][2] *= 0.0625f; s[nt][3] *= 0.0625f;
            mx0 = fmaxf(mx0, fmaxf(s[nt][0], s[nt][1]));
            mx1 = fmaxf(mx1, fmaxf(s[nt][2], s[nt][3]));
        }
        mx0 = fmaxf(mx0, __shfl_xor_sync(0xffffffffu, mx0, 1));
        mx0 = fmaxf(mx0, __shfl_xor_sync(0xffffffffu, mx0, 2));
        mx1 = fmaxf(mx1, __shfl_xor_sync(0xffffffffu, mx1, 1));
        mx1 = fmaxf(mx1, __shfl_xor_sync(0xffffffffu, mx1, 2));
        float mn0 = fmaxf(m0_, mx0), mn1 = fmaxf(m1_, mx1);
        float cr0 = __expf(m0_ - mn0), cr1 = __expf(m1_ - mn1);
        m0_ = mn0; m1_ = mn1;
        float sum0 = 0.f, sum1 = 0.f;
#pragma unroll
        for (int nt = 0; nt < 2; nt++) {
            s[nt][0] = __expf(s[nt][0] - mn0); sum0 += s[nt][0];
            s[nt][1] = __expf(s[nt][1] - mn0); sum0 += s[nt][1];
            s[nt][2] = __expf(s[nt][2] - mn1); sum1 += s[nt][2];
            s[nt][3] = __expf(s[nt][3] - mn1); sum1 += s[nt][3];
        }
        sum0 += __shfl_xor_sync(0xffffffffu, sum0, 1);
        sum0 += __shfl_xor_sync(0xffffffffu, sum0, 2);
        sum1 += __shfl_xor_sync(0xffffffffu, sum1, 1);
        sum1 += __shfl_xor_sync(0xffffffffu, sum1, 2);
        l0_ = l0_ * cr0 + sum0;
        l1_ = l1_ * cr1 + sum1;
#pragma unroll
        for (int nt = 0; nt < 32; nt++) {
            o[nt][0] *= cr0; o[nt][1] *= cr0;
            o[nt][2] *= cr1; o[nt][3] *= cr1;
        }

        uint32_t pah[4];
        pah[0] = pack_h2(s[0][0], s[0][1]);
        pah[1] = pack_h2(s[0][2], s[0][3]);
        pah[2] = pack_h2(s[1][0], s[1][1]);
        pah[3] = pack_h2(s[1][2], s[1][3]);
#pragma unroll
        for (int n2 = 0; n2 < 16; n2++) {
            uint32_t r[4], vh0[2], vh1[2];
            uint32_t va = base + 8192 + (n2 >> 2) * 2048 +
                          SWZ128(rV * 128 + (n2 & 3) * 32 + cV);
            ldmx4t(r, va);
            vh0[0] = r[0]; vh0[1] = r[1]; vh1[0] = r[2]; vh1[1] = r[3];
            mma_f32(o[2*n2],   pah, vh0);
            mma_f32(o[2*n2+1], pah, vh1);
        }
        __syncthreads();
    }

    float inv0 = 1.f / l0_, inv1 = 1.f / l1_;
    const long row0 = (long)(b * Sx + m0 + wid * 16 + gid) * Hx + h * 256;
    const long row1 = row0 + 8 * Hx;
#pragma unroll
    for (int nt = 0; nt < 32; nt++) {
        int d = nt * 8 + tig * 2;
        *(__half2*)(chi + row0 + d) = __halves2half2(
            __float2half(o[nt][0] * inv0), __float2half(o[nt][1] * inv0));
        *(__half2*)(chi + row1 + d) = __halves2half2(
            __float2half(o[nt][2] * inv1), __float2half(o[nt][3] * inv1));
    }
}

// ---------------------------------------------------------------------------
// conversions
// ---------------------------------------------------------------------------
struct WPack {
    const float* src[8];
    __half* dhi[8];
    int N[8];
    int tileOff[9];
};

__global__ void wsplit_all(WPack p)
{
    __shared__ float t[32][33];
    int bid = blockIdx.x;
    int w = 0;
    while (bid >= p.tileOff[w + 1]) w++;
    int tt = bid - p.tileOff[w];
    int ntx = p.N[w] >> 5;
    int n0 = (tt % ntx) * 32, k0 = (tt / ntx) * 32;
    const float* src = p.src[w];
    __half* hi = p.dhi[w];
    int N = p.N[w];
    int tx = threadIdx.x, ty = threadIdx.y;
    for (int j = ty; j < 32; j += 8)
        t[j][tx] = src[(long)(k0 + j) * N + n0 + tx];
    __syncthreads();
    for (int j = ty; j < 32; j += 8) {
        long o = (long)(n0 + j) * 1024 + k0 + tx;
        hi[o] = __float2half(t[tx][j]);
    }
}

__global__ void bcat_k(const float* __restrict__ bq, const float* __restrict__ bk,
                       const float* __restrict__ bv, float* __restrict__ dst)
{
    int i = blockIdx.x * 256 + threadIdx.x;
    if (i < 1024) dst[i] = bq[i];
    else if (i < 2048) dst[i] = bk[i - 1024];
    else if (i < 3072) dst[i] = bv[i - 2048];
}

// Fused: per row — xs_hi conversion + mod gate (amvec computed in-block)
__global__ void mod_k(const float* __restrict__ X, const float* __restrict__ cgW,
                      const float* __restrict__ cons, const float* __restrict__ amW,
                      const float* __restrict__ amb, const float* __restrict__ cgb,
                      __half* __restrict__ xs_hi, float* __restrict__ mod)
{
    __shared__ float xs[Hx];
    __shared__ float part[8][NHx];
    __shared__ float amv_s[NHx];
    int row = blockIdx.x;
    const float* x = X + (long)row * Hx;
    if (threadIdx.x < NHx) {
        int n = threadIdx.x;
        float s = amb[n] + cgb[n];
#pragma unroll
        for (int k = 0; k < 16; k++) s += cons[k] * amW[k * NHx + n];
        amv_s[n] = s;
    }
    for (int i = threadIdx.x; i < Hx; i += 128) {
        float v = x[i];
        xs[i] = v;
        xs_hi[(long)row * Hx + i] = __float2half(v);
    }
    __syncthreads();
    int n = threadIdx.x & 15;
    int g = threadIdx.x >> 4;
    float s = 0.f;
    for (int k = g; k < Hx; k += 8) s += xs[k] * cgW[k * NHx + n];
    part[g][n] = s;
    __syncthreads();
    if (threadIdx.x < NHx) {
        float t = amv_s[threadIdx.x];
#pragma unroll
        for (int gg = 0; gg < 8; gg++) t += part[gg][threadIdx.x];
        mod[(long)row * NHx + threadIdx.x] = 1.f / (1.f + __expf(-t));
    }
}

// ---------------------------------------------------------------------------
// Host side
// ---------------------------------------------------------------------------
template<typename T>
static T* symaddr(const void* sym) {
    void* p = nullptr;
    cudaGetSymbolAddress(&p, sym);
    return (T*)p;
}
typedef __half hf;

extern "C" void kernel_launch(void* const* d_in, const int* in_sizes, int n_in,
                              void* d_out, int out_size)
{
    (void)in_sizes; (void)n_in; (void)out_size;
    const float* X      = (const float*)d_in[0];
    const float* cons   = (const float*)d_in[1];
    const float* Wq     = (const float*)d_in[2];
    const float* bq     = (const float*)d_in[3];
    const float* Wk     = (const float*)d_in[4];
    const float* bk     = (const float*)d_in[5];
    const float* Wv     = (const float*)d_in[6];
    const float* bv     = (const float*)d_in[7];
    const float* cgW    = (const float*)d_in[8];
    const float* cgb    = (const float*)d_in[9];
    const float* amW    = (const float*)d_in[10];
    const float* amb    = (const float*)d_in[11];
    const float* caWin  = (const float*)d_in[12];
    const float* cabin  = (const float*)d_in[13];
    const float* caWout = (const float*)d_in[14];
    const float* cabout = (const float*)d_in[15];
    const float* mcWin  = (const float*)d_in[16];
    const float* mcbin  = (const float*)d_in[17];
    const float* mcWout = (const float*)d_in[18];
    const float* mcbout = (const float*)d_in[19];
    const float* Wo     = (const float*)d_in[20];
    const float* bo     = (const float*)d_in[21];
    float* out = (float*)d_out;

    hf *xs_hi = symaddr<hf>(g_xs_hi);
    hf *wqkvT_hi = symaddr<hf>(g_wqkvT_hi);
    hf *caWinT_hi = symaddr<hf>(g_caWinT_hi);
    hf *caWoutT_hi = symaddr<hf>(g_caWoutT_hi);
    hf *mcWinT_hi = symaddr<hf>(g_mcWinT_hi);
    hf *mcWoutT_hi = symaddr<hf>(g_mcWoutT_hi);
    hf *woT_hi = symaddr<hf>(g_woT_hi);
    hf *qk_hi = symaddr<hf>(g_qk_hi);
    hf *vT_hi = symaddr<hf>(g_vT_hi);
    hf *qkv_hi = symaddr<hf>(g_qkv_hi);
    hf *ctx2_hi = symaddr<hf>(g_ctx2_hi);
    hf *ctxb_hi = symaddr<hf>(g_ctxb_hi);
    hf *ctxm_hi = symaddr<hf>(g_ctxm_hi);
    float *ctx = symaddr<float>(g_ctx), *ctxb = symaddr<float>(g_ctxb);
    float *mod = symaddr<float>(g_mod);
    float *bqkv = symaddr<float>(g_bqkv);

    const int SMG  = 2 * 32768;          // 65536, 2 CTAs/SM
    const int SMFA = 16384 + 2 * 16384;  // 49152
    const int SMFB = 32768 + 2 * 16384;  // 65536, 2 CTAs/SM
    cudaFuncSetAttribute(gemm128,      cudaFuncAttributeMaxDynamicSharedMemorySize, SMG);
    cudaFuncSetAttribute(flash_main,   cudaFuncAttributeMaxDynamicSharedMemorySize, SMFA);
    cudaFuncSetAttribute(flash_branch, cudaFuncAttributeMaxDynamicSharedMemorySize, SMFB);

    const long SH = (long)Sx * Hx;
    dim3 tb(32, 8);
    dim3 gProj(Hx/128, MB/128, 1);       // 8 x 32 = 256 CTAs
    dim3 gQKV(3*Hx/128, MB/128, 1);      // 24 x 32 = 768 CTAs

    WPack wp;
    wp.src[0] = Wq;     wp.dhi[0] = wqkvT_hi;               wp.N[0] = Hx;
    wp.src[1] = Wk;     wp.dhi[1] = wqkvT_hi + Hx * Hx;     wp.N[1] = Hx;
    wp.src[2] = Wv;     wp.dhi[2] = wqkvT_hi + 2 * Hx * Hx; wp.N[2] = Hx;
    wp.src[3] = caWin;  wp.dhi[3] = caWinT_hi;  wp.N[3] = 3 * Hx;
    wp.src[4] = caWout; wp.dhi[4] = caWoutT_hi; wp.N[4] = Hx;
    wp.src[5] = mcWin;  wp.dhi[5] = mcWinT_hi;  wp.N[5] = 3 * Hx;
    wp.src[6] = mcWout; wp.dhi[6] = mcWoutT_hi; wp.N[6] = Hx;
    wp.src[7] = Wo;     wp.dhi[7] = woT_hi;     wp.N[7] = Hx;
    wp.tileOff[0] = 0;
    for (int i = 0; i < 8; i++)
        wp.tileOff[i + 1] = wp.tileOff[i] + (wp.N[i] / 32) * (Hx / 32);

    // prep
    bcat_k<<<12, 256>>>(bq, bk, bv, bqkv);                                  // 0
    wsplit_all<<<wp.tileOff[8], tb>>>(wp);                                  // 1
    mod_k<<<MB, 128>>>(X, cgW, cons, amW, amb, cgb, xs_hi, mod);            // 2

    // 3: merged QKV projection: Q,K -> qk (ldc 2048), V -> transposed vT
    gemm128<<<gQKV, 256, SMG>>>(xs_hi, Hx, 0, 0,
        wqkvT_hi, Hx, 0, 0,
        nullptr, qk_hi, 2 * Hx, 0, 0,
        vT_hi, 2 * Hx, 3 * Hx, SH,
        Hx, 1, bqkv, 1.f, nullptr, 0, 0.f);

    // 4: fused main attention -> ctx (fp32)
    flash_main<<<dim3(Sx/128, Bx * NHx), 256, SMFA>>>(
        qk_hi, vT_hi, mod, ctx);

    // ---- causal + meta branches ----
    for (int br = 0; br < 2; br++) {
        const hf* winT_hi = br ? mcWinT_hi : caWinT_hi;
        const hf* woutT_hi = br ? mcWoutT_hi : caWoutT_hi;
        const float* bin  = br ? mcbin  : cabin;
        const float* bout = br ? mcbout : cabout;
        const hf* a_hi = br ? ctxb_hi : xs_hi;

        // in-proj: qkv = A @ Win + bin (fp16 out)
        gemm128<<<gQKV, 256, SMG>>>(a_hi, Hx, 0, 0,
            winT_hi, Hx, 0, 0,
            nullptr, qkv_hi, 3 * Hx, 0, 0,
            nullptr, 0, 0, 0,
            Hx, 1, bin, 1.f, nullptr, 0, 0.f);
        // fused branch attention -> ctx2 (fp16)
        flash_branch<<<dim3(Sx/64, Bx * BR_HEADS), 128, SMFB>>>(
            qkv_hi, ctx2_hi);
        // out-proj + blend
        if (br == 0) {
            gemm128<<<gProj, 256, SMG>>>(ctx2_hi, Hx, 0, 0,
                woutT_hi, Hx, 0, 0,
                ctxb, ctxb_hi, Hx, 0, 0,
                nullptr, 0, 0, 0,
                Hx, 1, bout, CAUSAL_W, ctx, Hx, 1.f - CAUSAL_W);
        } else {
            gemm128<<<gProj, 256, SMG>>>(ctx2_hi, Hx, 0, 0,
                woutT_hi, Hx, 0, 0,
                nullptr, ctxm_hi, Hx, 0, 0,
                nullptr, 0, 0, 0,
                Hx, 1, bout, META_W, ctxb, Hx, 1.f - META_W);
        }
    }

    // ---- final projection ----
    gemm128<<<gProj, 256, SMG>>>(ctxm_hi, Hx, 0, 0,
        woT_hi, Hx, 0, 0,
        out, nullptr, Hx, 0, 0,
        nullptr, 0, 0, 0,
        Hx, 1, bo, 1.f, nullptr, 0, 0.f);
}